// round 15
// baseline (speedup 1.0000x reference)
#include <cuda_runtime.h>
#include <cuda_fp16.h>
#include <math.h>
#include <stdint.h>

#define SEQN  4096
#define BATCH 4
#define DIM   1024
#define NH    16
#define DHD   64
#define NL    32
#define WW    8
#define EE    4
#define BAND  16
#define NG    (SEQN / WW)
#define MROWS (BATCH * SEQN)
#define NSPLIT 8
#define CSIZE (BATCH * NH * NL * DHD)

__device__ float g_KcP[NSPLIT * CSIZE];
__device__ float g_VcP[NSPLIT * CSIZE];

__device__ __align__(16) __half g_D  [BATCH * SEQN * NH * NL];  // logits fp16
__device__ __align__(16) __half g_tmp[BATCH * SEQN * DIM];      // K pre-LN
__device__ __align__(16) __half g_tv [BATCH * SEQN * DIM];      // V pre-LN
__device__ __align__(16) __half g_Xh[MROWS * DIM];
__device__ __align__(16) __half g_Ch[MROWS * DIM];
__device__ __align__(16) __half g_Qh[BATCH * NH * SEQN * DHD];
__device__ __align__(16) __half g_Ql[BATCH * NH * SEQN * DHD];
__device__ __align__(16) __half g_KhF[BATCH * NH * SEQN * DHD];
__device__ __align__(16) __half g_VhF[BATCH * NH * SEQN * DHD];
__device__ __align__(16) __half g_Ph [BATCH * NH * NL * SEQN];
__device__ __align__(16) __half g_Kch[CSIZE];
__device__ __align__(16) __half g_Vch[CSIZE];
// weight rows: Q 0-1023, K 1024-2047, V 2048-3071, D 3072-3583, O 3584-4607
#define WOFF_O (3 * DIM * DIM + (NH * NL) * DIM)
#define WT_TOTAL (4 * DIM * DIM + (NH * NL) * DIM)
__device__ __align__(16) __half g_Wth[WT_TOTAL];

// =========================== common asm helpers ============================
__device__ __forceinline__ uint32_t smem_u32(const void* p) {
    uint32_t a;
    asm("{ .reg .u64 t; cvta.to.shared.u64 t, %1; cvt.u32.u64 %0, t; }" : "=r"(a) : "l"(p));
    return a;
}
#define CPA(dst, src) \
    asm volatile("cp.async.cg.shared.global [%0], [%1], 16;" :: "r"(dst), "l"(src))
#define CP_COMMIT() asm volatile("cp.async.commit_group;")
#define CP_WAIT(n)  asm volatile("cp.async.wait_group %0;" :: "n"(n))
#define LDSM4(R, addr) \
    asm volatile("ldmatrix.sync.aligned.m8n8.x4.shared.b16 {%0,%1,%2,%3}, [%4];" \
        : "=r"((R)[0]), "=r"((R)[1]), "=r"((R)[2]), "=r"((R)[3]) : "r"(addr))
#define LDSM4T(R, addr) \
    asm volatile("ldmatrix.sync.aligned.m8n8.x4.trans.shared.b16 {%0,%1,%2,%3}, [%4];" \
        : "=r"((R)[0]), "=r"((R)[1]), "=r"((R)[2]), "=r"((R)[3]) : "r"(addr))
#define MMA16816(d, a, b0, b1) \
    asm volatile("mma.sync.aligned.m16n8k16.row.col.f32.f16.f16.f32 " \
        "{%0,%1,%2,%3}, {%4,%5,%6,%7}, {%8,%9}, {%0,%1,%2,%3};" \
        : "+f"((d)[0]), "+f"((d)[1]), "+f"((d)[2]), "+f"((d)[3]) \
        : "r"((a)[0]), "r"((a)[1]), "r"((a)[2]), "r"((a)[3]), "r"(b0), "r"(b1))

__device__ __forceinline__ uint32_t pack_h2(float lo, float hi) {
    __half2 h = __halves2half2(__float2half_rn(lo), __float2half_rn(hi));
    return *(uint32_t*)&h;
}

// =========================== HMMA GEMM core ================================
#define SROWB 80
#define TILEB (128 * SROWB)
#define NIT (DIM / 32)

template <int TERMS>
__device__ __forceinline__ void hgemm_main(
    const __half* Ah, const __half* Al, const __half* Bh,
    int bm, int bn, uint32_t sb, int tid, float acc[2][8][4])
{
    constexpr uint32_t STG = (TERMS + 1) * TILEB;
    constexpr uint32_t oAH = 0;
    constexpr uint32_t oAL = TILEB;
    constexpr uint32_t oBH = (TERMS >= 2) ? 2 * TILEB : TILEB;

    const int lane = tid & 31, wid = tid >> 5;
    const int wm = wid & 3, wn = wid >> 2;
    const int lr0 = tid >> 2;
    const size_t aoff0 = ((size_t)(bm + lr0) << 10) + (size_t)(tid & 3) * 8;
    const size_t aoff1 = aoff0 + ((size_t)64 << 10);
    const size_t boff0 = ((size_t)(bn + lr0) << 10) + (size_t)(tid & 3) * 8;
    const size_t boff1 = boff0 + ((size_t)64 << 10);
    const uint32_t d0 = (uint32_t)lr0 * SROWB + (tid & 3) * 16;
    const uint32_t d1 = d0 + 64 * SROWB;

    CPA(sb + oAH + d0, Ah + aoff0); CPA(sb + oAH + d1, Ah + aoff1);
    if (TERMS >= 2) { CPA(sb + oAL + d0, Al + aoff0); CPA(sb + oAL + d1, Al + aoff1); }
    CPA(sb + oBH + d0, Bh + boff0); CPA(sb + oBH + d1, Bh + boff1);
    CP_COMMIT();

#pragma unroll
    for (int i = 0; i < 2; i++)
#pragma unroll
        for (int j = 0; j < 8; j++)
#pragma unroll
            for (int k = 0; k < 4; k++) acc[i][j][k] = 0.f;

    const uint32_t aBase = (uint32_t)(wm * 32 + (lane & 15)) * SROWB + (lane >> 4) * 16;
    const uint32_t bBase = (uint32_t)(wn * 64 + ((lane >> 4) & 1) * 8 + (lane & 7)) * SROWB
                           + ((lane >> 3) & 1) * 16;

    for (int it = 0; it < NIT; it++) {
        const uint32_t ps = (it & 1) * STG;
        if (it + 1 < NIT) {
            const uint32_t ns = ((it + 1) & 1) * STG;
            const int kb = (it + 1) * 32;
            CPA(sb + ns + oAH + d0, Ah + aoff0 + kb); CPA(sb + ns + oAH + d1, Ah + aoff1 + kb);
            if (TERMS >= 2) {
                CPA(sb + ns + oAL + d0, Al + aoff0 + kb); CPA(sb + ns + oAL + d1, Al + aoff1 + kb);
            }
            CPA(sb + ns + oBH + d0, Bh + boff0 + kb); CPA(sb + ns + oBH + d1, Bh + boff1 + kb);
            CP_COMMIT();
            CP_WAIT(1);
        } else {
            CP_WAIT(0);
        }
        __syncthreads();

        const uint32_t sAH = sb + ps + oAH + aBase;
        const uint32_t sAL = sb + ps + oAL + aBase;
        const uint32_t sBH = sb + ps + oBH + bBase;
#pragma unroll
        for (int ks = 0; ks < 2; ks++) {
            const uint32_t ko = ks * 32;
            uint32_t ah[2][4], al[2][4];
            LDSM4(ah[0], sAH + ko);
            LDSM4(ah[1], sAH + ko + 16 * SROWB);
            if (TERMS >= 2) {
                LDSM4(al[0], sAL + ko);
                LDSM4(al[1], sAL + ko + 16 * SROWB);
            }
#pragma unroll
            for (int q = 0; q < 4; q++) {
                uint32_t bh[4];
                LDSM4(bh, sBH + ko + q * 16 * SROWB);
#pragma unroll
                for (int mt = 0; mt < 2; mt++) {
                    MMA16816(acc[mt][2 * q + 0], ah[mt], bh[0], bh[1]);
                    MMA16816(acc[mt][2 * q + 1], ah[mt], bh[2], bh[3]);
                    if (TERMS >= 2) {
                        MMA16816(acc[mt][2 * q + 0], al[mt], bh[0], bh[1]);
                        MMA16816(acc[mt][2 * q + 1], al[mt], bh[2], bh[3]);
                    }
                }
            }
        }
        __syncthreads();
    }
}
#define GEMM_SMEM1 (2 * 2 * TILEB)

// ---- fused Q/K/V/D GEMM (1-term); Q fp16 hi/lo, K/V/D fp16 ----
__global__ __launch_bounds__(256, 2) void hgemm_qkvd(
    const __half* __restrict__ Ah, const __half* __restrict__ Bh,
    const float* __restrict__ bq, const float* __restrict__ bk,
    const float* __restrict__ bv, const float* __restrict__ bd,
    __half* __restrict__ outQh, __half* __restrict__ outQl,
    __half* __restrict__ outK, __half* __restrict__ outV, __half* __restrict__ outD)
{
    extern __shared__ __align__(16) char smem[];
    const uint32_t sb = smem_u32(smem);
    const int tid = threadIdx.x, wid = tid >> 5, lane = tid & 31;
    const int bn = blockIdx.x * 128, bm = blockIdx.y * 128;
    float acc[2][8][4];
    hgemm_main<1>(Ah, nullptr, Bh, bm, bn, sb, tid, acc);

    const int seg = bn >> 10;
    const int cl = bn & 1023;
    const float* bias = seg == 0 ? bq : seg == 1 ? bk : seg == 2 ? bv : bd;
    const float scale = seg == 0 ? 0.125f : 1.f;
    const int wm = wid & 3, wn = wid >> 2;
    const int r0 = bm + wm * 32 + (lane >> 2);
    const int c0 = cl + wn * 64 + (lane & 3) * 2;
#pragma unroll
    for (int mt = 0; mt < 2; mt++) {
#pragma unroll
        for (int hf = 0; hf < 2; hf++) {
            const int r = r0 + mt * 16 + hf * 8;
            const int bb = r >> 12, ss = r & (SEQN - 1);
#pragma unroll
            for (int nt = 0; nt < 8; nt++) {
                const int col = c0 + nt * 8;
                const float2 bv2 = *(const float2*)(bias + col);
                float vx = (acc[mt][nt][hf * 2 + 0] + bv2.x) * scale;
                float vy = (acc[mt][nt][hf * 2 + 1] + bv2.y) * scale;
                if (seg == 0) {
                    size_t o = ((size_t)(bb * NH + (col >> 6)) * SEQN + ss) * DHD + (col & 63);
                    __half hx = __float2half_rn(vx), hy = __float2half_rn(vy);
                    *(__half2*)(outQh + o) = __halves2half2(hx, hy);
                    *(__half2*)(outQl + o) = __halves2half2(
                        __float2half_rn(vx - __half2float(hx)),
                        __float2half_rn(vy - __half2float(hy)));
                } else if (seg == 3) {
                    *(__half2*)(outD + (size_t)r * (NH * NL) + col) =
                        __halves2half2(__float2half_rn(vx), __float2half_rn(vy));
                } else {
                    __half* op = (seg == 1) ? outK : outV;
                    *(__half2*)(op + (size_t)r * DIM + col) =
                        __halves2half2(__float2half_rn(vx), __float2half_rn(vy));
                }
            }
        }
    }
}

// ---- output GEMM (1-term): out = C @ Wo + bo, (s,b,DIM) ----
__global__ __launch_bounds__(256, 2) void hgemm_o(
    const __half* __restrict__ Ah, const __half* __restrict__ Bh,
    const float* __restrict__ bias, float* __restrict__ out)
{
    extern __shared__ __align__(16) char smem[];
    const uint32_t sb = smem_u32(smem);
    const int tid = threadIdx.x, wid = tid >> 5, lane = tid & 31;
    const int bn = blockIdx.x * 128, bm = blockIdx.y * 128;
    float acc[2][8][4];
    hgemm_main<1>(Ah, nullptr, Bh, bm, bn, sb, tid, acc);

    const int wm = wid & 3, wn = wid >> 2;
    const int r0 = bm + wm * 32 + (lane >> 2);
    const int c0 = bn + wn * 64 + (lane & 3) * 2;
#pragma unroll
    for (int mt = 0; mt < 2; mt++) {
#pragma unroll
        for (int hf = 0; hf < 2; hf++) {
            const int r = r0 + mt * 16 + hf * 8;
            const int bb = r >> 12, ss = r & (SEQN - 1);
#pragma unroll
            for (int nt = 0; nt < 8; nt++) {
                const int col = c0 + nt * 8;
                const float2 bv2 = *(const float2*)(bias + col);
                *(float2*)(out + ((size_t)ss * BATCH + bb) * DIM + col) =
                    make_float2(acc[mt][nt][hf * 2 + 0] + bv2.x,
                                acc[mt][nt][hf * 2 + 1] + bv2.y);
            }
        }
    }
}

// ================= HMMA compress: Kc/Vc partials (1-term) ==================
#define CPROW 144
#define CPS_PH 0
#define CPS_K  (32 * CPROW)
#define CPS_V  (96 * CPROW)
#define CP_STG (160 * CPROW)
#define COMP_SMEM (2 * CP_STG)

__global__ __launch_bounds__(256, 2) void compress_hmma(
    const __half* __restrict__ Ph,
    const __half* __restrict__ Kh, const __half* __restrict__ Vh,
    float* __restrict__ partK, float* __restrict__ partV)
{
    extern __shared__ __align__(16) char smem[];
    const uint32_t sb = smem_u32(smem);
    const int bh = blockIdx.x, sp = blockIdx.y;
    const int b = bh >> 4, h = bh & 15;
    const int tid = threadIdx.x, lane = tid & 31, wid = tid >> 5;

    const size_t pbase = ((size_t)(b * (NH * NL) + h * NL)) * SEQN + sp * 512;
    const size_t kbase = ((size_t)bh * SEQN + sp * 512) * DHD;

    const int prow = tid >> 3, pseg = tid & 7;
    const uint32_t pDst = prow * CPROW + pseg * 16;
    const size_t pSrc = (size_t)prow * SEQN + pseg * 8;
    const uint32_t kDst0 = prow * CPROW + pseg * 16;
    const uint32_t kDst1 = (prow + 32) * CPROW + pseg * 16;
    const size_t kSrc0 = (size_t)prow * DHD + pseg * 8;
    const size_t kSrc1 = (size_t)(prow + 32) * DHD + pseg * 8;

    CPA(sb + CPS_PH + pDst, Ph + pbase + pSrc);
    CPA(sb + CPS_K + kDst0, Kh + kbase + kSrc0);
    CPA(sb + CPS_K + kDst1, Kh + kbase + kSrc1);
    CPA(sb + CPS_V + kDst0, Vh + kbase + kSrc0);
    CPA(sb + CPS_V + kDst1, Vh + kbase + kSrc1);
    CP_COMMIT();

    float acc[4][4];
#pragma unroll
    for (int i = 0; i < 4; i++)
#pragma unroll
        for (int j = 0; j < 4; j++) acc[i][j] = 0.f;

    const int outv = wid >> 2;
    const int mt = wid & 1, nh2 = (wid >> 1) & 1;
    const uint32_t aOff = (uint32_t)(mt * 16 + (lane & 15)) * CPROW + (lane >> 4) * 16;
    const uint32_t bRow = (lane & 7) + ((lane >> 3) & 1) * 8;
    const uint32_t bCol = ((lane >> 4) & 1) * 16 + nh2 * 64;
    const uint32_t kvOff = outv ? CPS_V : CPS_K;

    for (int c = 0; c < 8; c++) {
        const uint32_t ps = (c & 1) * CP_STG;
        if (c + 1 < 8) {
            const uint32_t ns = ((c + 1) & 1) * CP_STG;
            const int so = (c + 1) * 64;
            CPA(sb + ns + CPS_PH + pDst, Ph + pbase + so + pSrc);
            CPA(sb + ns + CPS_K + kDst0, Kh + kbase + (size_t)so * DHD + kSrc0);
            CPA(sb + ns + CPS_K + kDst1, Kh + kbase + (size_t)so * DHD + kSrc1);
            CPA(sb + ns + CPS_V + kDst0, Vh + kbase + (size_t)so * DHD + kSrc0);
            CPA(sb + ns + CPS_V + kDst1, Vh + kbase + (size_t)so * DHD + kSrc1);
            CP_COMMIT();
            CP_WAIT(1);
        } else {
            CP_WAIT(0);
        }
        __syncthreads();

        const uint32_t sP0 = sb + ps + CPS_PH + aOff;
        const uint32_t sKV = sb + ps + kvOff;
#pragma unroll
        for (int ks = 0; ks < 4; ks++) {
            uint32_t ah[4], b0[4], b1[4];
            LDSM4(ah, sP0 + ks * 32);
            const uint32_t ba = sKV + (ks * 16 + bRow) * CPROW + bCol;
            LDSM4T(b0, ba);
            LDSM4T(b1, ba + 32);
            MMA16816(acc[0], ah, b0[0], b0[1]);
            MMA16816(acc[1], ah, b0[2], b0[3]);
            MMA16816(acc[2], ah, b1[0], b1[1]);
            MMA16816(acc[3], ah, b1[2], b1[3]);
        }
        __syncthreads();
    }

    float* outp = outv ? partV : partK;
    const size_t ob = (size_t)sp * CSIZE + (size_t)bh * NL * DHD;
    const int l0 = mt * 16 + (lane >> 2);
    const int db = nh2 * 32 + (lane & 3) * 2;
#pragma unroll
    for (int nt = 0; nt < 4; nt++) {
        const int d = db + nt * 8;
        *(float2*)(outp + ob + (size_t)l0 * DHD + d) = make_float2(acc[nt][0], acc[nt][1]);
        *(float2*)(outp + ob + (size_t)(l0 + 8) * DHD + d) = make_float2(acc[nt][2], acc[nt][3]);
    }
}

// ---- fp32 -> fp16 with (s,b)->(b,s) permute ----
__global__ __launch_bounds__(256) void split_perm_kernel(
    const float* __restrict__ X, __half* __restrict__ H)
{
    int i = blockIdx.x * 256 + threadIdx.x;
    int r = i >> 8, k4 = i & 255;
    int b = r >> 12, s = r & (SEQN - 1);
    float4 v = *((const float4*)X + ((size_t)s * BATCH + b) * 256 + k4);
    __half2* Hp = (__half2*)(H + (size_t)i * 4);
    Hp[0] = __halves2half2(__float2half_rn(v.x), __float2half_rn(v.y));
    Hp[1] = __halves2half2(__float2half_rn(v.z), __float2half_rn(v.w));
}

// ---- all 5 weight transposes (fp16) in one launch ----
__global__ void wsplit_all_kernel(
    const float* __restrict__ Wq, const float* __restrict__ Wk,
    const float* __restrict__ Wv, const float* __restrict__ Wd,
    const float* __restrict__ Wo, __half* __restrict__ Th)
{
    __shared__ float t[32][33];
    int z = blockIdx.z;
    int N = (z == 3) ? (NH * NL) : DIM;
    if (blockIdx.x * 32 >= N) return;
    const float* W = z == 0 ? Wq : z == 1 ? Wk : z == 2 ? Wv : z == 3 ? Wd : Wo;
    size_t woff = z <= 3 ? (size_t)z * DIM * DIM : (size_t)WOFF_O;
    int n0 = blockIdx.x * 32, k0 = blockIdx.y * 32;
    int x = threadIdx.x, y = threadIdx.y;
#pragma unroll
    for (int i = 0; i < 32; i += 8)
        t[y + i][x] = W[(size_t)(k0 + y + i) * N + n0 + x];
    __syncthreads();
#pragma unroll
    for (int i = 0; i < 32; i += 8)
        Th[woff + (size_t)(n0 + y + i) * DIM + k0 + x] = __float2half_rn(t[x][y + i]);
}

// ---- LayerNorm over DIM (fp16 in), head-split; fp16 out ----
__global__ __launch_bounds__(256) void ln_split2_kernel(
    const __half* __restrict__ XK, const __half* __restrict__ XV,
    const float* __restrict__ gamma, const float* __restrict__ beta,
    __half* __restrict__ oKh, __half* __restrict__ oVh)
{
    __shared__ float shs[8], shq[8];
    int r = blockIdx.x, tid = threadIdx.x;
    const __half* X = blockIdx.y ? XV : XK;
    __half* outh = blockIdx.y ? oVh : oKh;
    const __half2* xp = (const __half2*)(X + (size_t)r * DIM) + tid * 2;
    float2 a = __half22float2(xp[0]);
    float2 bq2 = __half22float2(xp[1]);
    float vx = a.x, vy = a.y, vz = bq2.x, vw = bq2.y;
    float s = vx + vy + vz + vw;
    float q = vx*vx + vy*vy + vz*vz + vw*vw;
    int lane = tid & 31, wid = tid >> 5;
#pragma unroll
    for (int o = 16; o; o >>= 1) {
        s += __shfl_xor_sync(~0u, s, o); q += __shfl_xor_sync(~0u, q, o);
    }
    if (lane == 0) { shs[wid] = s; shq[wid] = q; }
    __syncthreads();
    if (tid == 0) {
        float ts = 0, tq = 0;
        for (int i = 0; i < 8; i++) { ts += shs[i]; tq += shq[i]; }
        shs[0] = ts; shq[0] = tq;
    }
    __syncthreads();
    float mean = shs[0] * (1.f / DIM);
    float rstd = rsqrtf(shq[0] * (1.f / DIM) - mean * mean + 1e-5f);
    int c = tid * 4;
    float4 g4 = ((const float4*)gamma)[tid], b4 = ((const float4*)beta)[tid];
    float o0 = (vx - mean) * rstd * g4.x + b4.x;
    float o1 = (vy - mean) * rstd * g4.y + b4.y;
    float o2 = (vz - mean) * rstd * g4.z + b4.z;
    float o3 = (vw - mean) * rstd * g4.w + b4.w;
    int b = r >> 12, sq = r & (SEQN - 1);
    size_t base = ((size_t)(b * NH + (c >> 6)) * SEQN + sq) * DHD + (c & 63);
    __half2* hp = (__half2*)(outh + base);
    hp[0] = __halves2half2(__float2half_rn(o0), __float2half_rn(o1));
    hp[1] = __halves2half2(__float2half_rn(o2), __float2half_rn(o3));
}

// ---- fused column softmax: D (b,s,512) fp16 -> Ph (b,512,s) fp16 ----
// Block = (32 columns, batch b). No max subtraction (|logit| <~ 4, safe).
__global__ __launch_bounds__(256) void softmax_col_kernel(
    const __half* __restrict__ D, __half* __restrict__ Ph)
{
    __shared__ float red[8][33];
    __shared__ __half tile[32][40];
    const int b = blockIdx.y, c0 = blockIdx.x * 32;
    const int tid = threadIdx.x;
    const int x = tid & 31, y = tid >> 5;   // x: column, y: s-stripe
    const __half* Db = D + (size_t)b * SEQN * (NH * NL);

    float sum = 0.f;
    for (int s = y; s < SEQN; s += 8)
        sum += __expf(__half2float(Db[(size_t)s * (NH * NL) + c0 + x]));
    red[y][x] = sum;
    __syncthreads();
    if (y == 0) {
        float t = 0;
#pragma unroll
        for (int i = 0; i < 8; i++) t += red[i][x];
        red[0][x] = 1.f / t;
    }
    __syncthreads();
    const float inv = red[0][x];

    __half* Pb = Ph + (size_t)b * (NH * NL) * SEQN;
    for (int st = 0; st < SEQN; st += 32) {
        // load + exp + transpose-stage (thread (x,y) covers rows st+y, st+y+8, ...)
#pragma unroll
        for (int rr = 0; rr < 4; rr++) {
            const int r = y + rr * 8;
            float v = __expf(__half2float(Db[(size_t)(st + r) * (NH * NL) + c0 + x])) * inv;
            tile[x][r] = __float2half_rn(v);
        }
        __syncthreads();
        // write: warp y covers columns y, y+8, y+16, y+24; lane x = s offset
#pragma unroll
        for (int cc = 0; cc < 4; cc++) {
            const int c = cc * 8 + y;
            Pb[(size_t)(c0 + c) * SEQN + st + x] = tile[c][x];
        }
        __syncthreads();
    }
}

// ---- reduce partials + LN for Kc/Vc; fp16 hi outputs only ----
__global__ __launch_bounds__(256) void compress_ln_kernel(
    const float* __restrict__ partK, const float* __restrict__ partV,
    const float* __restrict__ gamma, const float* __restrict__ beta,
    __half* __restrict__ oKh, __half* __restrict__ oVh)
{
    __shared__ float shs[8], shq[8];
    int bl = blockIdx.x, b = bl >> 5, l = bl & 31;
    const float* part = blockIdx.y ? partV : partK;
    __half* outh = blockIdx.y ? oVh : oKh;
    int tid = threadIdx.x, c = tid * 4;
    size_t base = ((size_t)(b * NH + (c >> 6)) * NL + l) * DHD + (c & 63);
    float4 acc = make_float4(0, 0, 0, 0);
#pragma unroll
    for (int sp = 0; sp < NSPLIT; sp++) {
        float4 p = *(const float4*)(part + (size_t)sp * CSIZE + base);
        acc.x += p.x; acc.y += p.y; acc.z += p.z; acc.w += p.w;
    }
    float s = acc.x + acc.y + acc.z + acc.w;
    float q = acc.x*acc.x + acc.y*acc.y + acc.z*acc.z + acc.w*acc.w;
    int lane = tid & 31, wid = tid >> 5;
#pragma unroll
    for (int o = 16; o; o >>= 1) {
        s += __shfl_xor_sync(~0u, s, o); q += __shfl_xor_sync(~0u, q, o);
    }
    if (lane == 0) { shs[wid] = s; shq[wid] = q; }
    __syncthreads();
    if (tid == 0) {
        float ts = 0, tq = 0;
        for (int i = 0; i < 8; i++) { ts += shs[i]; tq += shq[i]; }
        shs[0] = ts; shq[0] = tq;
    }
    __syncthreads();
    float mean = shs[0] * (1.f / DIM);
    float rstd = rsqrtf(shq[0] * (1.f / DIM) - mean * mean + 1e-5f);
    float4 g4 = ((const float4*)gamma)[tid], b4 = ((const float4*)beta)[tid];
    __half2* hp = (__half2*)(outh + base);
    hp[0] = __halves2half2(__float2half_rn((acc.x - mean) * rstd * g4.x + b4.x),
                           __float2half_rn((acc.y - mean) * rstd * g4.y + b4.y));
    hp[1] = __halves2half2(__float2half_rn((acc.z - mean) * rstd * g4.z + b4.z),
                           __float2half_rn((acc.w - mean) * rstd * g4.w + b4.w));
}

// ================= HMMA attention (QK 2-term, PV 1-term) ===================
#define AROWB 144
#define AS_QH 0
#define AS_QL (64 * AROWB)
#define AS_KH (128 * AROWB)
#define AS_VH (240 * AROWB)
#define ATTN_SMEM (352 * AROWB)    // 50688 B

__global__ __launch_bounds__(128, 3) void attn_hmma(
    const __half* __restrict__ Qh, const __half* __restrict__ Ql,
    const __half* __restrict__ Kh, const __half* __restrict__ Vh,
    const __half* __restrict__ Kch, const __half* __restrict__ Vch,
    __half* __restrict__ Ch)
{
    extern __shared__ __align__(16) char smem[];
    const uint32_t sb = smem_u32(smem);
    const int h = blockIdx.y, bb = blockIdx.z;
    const int bh = bb * NH + h;
    const int qbase = blockIdx.x * 64;
    const int tid = threadIdx.x, lane = tid & 31, warp = tid >> 5;

    for (int idx = tid; idx < 112 * 8; idx += 128) {
        const int row = idx >> 3, seg = idx & 7;
        const uint32_t dst = row * AROWB + seg * 16;
        uint4 kh4 = {0,0,0,0}, vh4 = {0,0,0,0};
        if (row < 32) {
            size_t src = ((size_t)bh * NL + row) * DHD + seg * 8;
            kh4 = *(const uint4*)(Kch + src);
            vh4 = *(const uint4*)(Vch + src);
        } else {
            const int seq = qbase - EE + (row - 32);
            if (seq >= 0 && seq < SEQN) {
                size_t src = ((size_t)bh * SEQN + seq) * DHD + seg * 8;
                kh4 = *(const uint4*)(Kh + src);
                vh4 = *(const uint4*)(Vh + src);
            }
        }
        *(uint4*)(smem + AS_KH + dst) = kh4;
        *(uint4*)(smem + AS_VH + dst) = vh4;
    }
    for (int idx = tid; idx < 64 * 8; idx += 128) {
        const int row = idx >> 3, seg = idx & 7;
        const uint32_t dst = row * AROWB + seg * 16;
        size_t src = ((size_t)bh * SEQN + qbase + row) * DHD + seg * 8;
        *(uint4*)(smem + AS_QH + dst) = *(const uint4*)(Qh + src);
        *(uint4*)(smem + AS_QL + dst) = *(const uint4*)(Ql + src);
    }
    __syncthreads();

    const int r0 = warp * 16;
    float sacc[14][4];
#pragma unroll
    for (int j = 0; j < 14; j++)
#pragma unroll
        for (int e = 0; e < 4; e++) sacc[j][e] = 0.f;

    const uint32_t aOff = (uint32_t)(r0 + (lane & 15)) * AROWB + (lane >> 4) * 16;
    const uint32_t bOffS = (uint32_t)(((lane >> 4) & 1) * 8 + (lane & 7)) * AROWB
                           + ((lane >> 3) & 1) * 16;
#pragma unroll
    for (int ks = 0; ks < 4; ks++) {
        uint32_t ah[4], al[4];
        LDSM4(ah, sb + AS_QH + aOff + ks * 32);
        LDSM4(al, sb + AS_QL + aOff + ks * 32);
#pragma unroll
        for (int i = 0; i < 7; i++) {
            const uint32_t bo = bOffS + (uint32_t)(i * 16) * AROWB + ks * 32;
            uint32_t bh4[4];
            LDSM4(bh4, sb + AS_KH + bo);
            MMA16816(sacc[2*i+0], ah, bh4[0], bh4[1]);
            MMA16816(sacc[2*i+0], al, bh4[0], bh4[1]);
            MMA16816(sacc[2*i+1], ah, bh4[2], bh4[3]);
            MMA16816(sacc[2*i+1], al, bh4[2], bh4[3]);
        }
    }

    const int ra = r0 + (lane >> 2), rb = ra + 8;
    const int ga = ra >> 3, gb = rb >> 3;
    float mxa = -1e30f, mxb = -1e30f;
    bool vld[14][4];
#pragma unroll
    for (int j = 0; j < 14; j++) {
#pragma unroll
        for (int e = 0; e < 2; e++) {
            const int col = j * 8 + (lane & 3) * 2 + e;
            bool va, vb;
            if (col < 32) { va = true; vb = true; }
            else {
                const int w = col - 32;
                const int seq = qbase - EE + w;
                const bool sv = (seq >= 0) && (seq < SEQN);
                va = sv && (w >= ga * 8) && (w < ga * 8 + BAND);
                vb = sv && (w >= gb * 8) && (w < gb * 8 + BAND);
            }
            vld[j][e] = va; vld[j][2 + e] = vb;
            if (va) mxa = fmaxf(mxa, sacc[j][e]);
            if (vb) mxb = fmaxf(mxb, sacc[j][2 + e]);
        }
    }
#pragma unroll
    for (int o = 1; o <= 2; o <<= 1) {
        mxa = fmaxf(mxa, __shfl_xor_sync(~0u, mxa, o));
        mxb = fmaxf(mxb, __shfl_xor_sync(~0u, mxb, o));
    }
    float sma = 0.f, smb = 0.f;
#pragma unroll
    for (int j = 0; j < 14; j++) {
#pragma unroll
        for (int e = 0; e < 2; e++) {
            float pa = vld[j][e]     ? __expf(sacc[j][e]     - mxa) : 0.f;
            float pb = vld[j][2 + e] ? __expf(sacc[j][2 + e] - mxb) : 0.f;
            sacc[j][e] = pa; sacc[j][2 + e] = pb;
            sma += pa; smb += pb;
        }
    }
#pragma unroll
    for (int o = 1; o <= 2; o <<= 1) {
        sma += __shfl_xor_sync(~0u, sma, o);
        smb += __shfl_xor_sync(~0u, smb, o);
    }
    const float iva = 1.f / sma, ivb = 1.f / smb;
#pragma unroll
    for (int j = 0; j < 14; j++) {
        sacc[j][0] *= iva; sacc[j][1] *= iva;
        sacc[j][2] *= ivb; sacc[j][3] *= ivb;
    }

    float pacc[8][4];
#pragma unroll
    for (int i = 0; i < 8; i++)
#pragma unroll
        for (int e = 0; e < 4; e++) pacc[i][e] = 0.f;

    const uint32_t bRowV = (uint32_t)((lane & 7) + ((lane >> 3) & 1) * 8);
    const uint32_t bColV = ((lane >> 4) & 1) * 16;
#pragma unroll
    for (int ks = 0; ks < 7; ks++) {
        const int j0 = 2 * ks, j1 = 2 * ks + 1;
        uint32_t Pf[4];
        Pf[0] = pack_h2(sacc[j0][0], sacc[j0][1]);
        Pf[1] = pack_h2(sacc[j0][2], sacc[j0][3]);
        Pf[2] = pack_h2(sacc[j1][0], sacc[j1][1]);
        Pf[3] = pack_h2(sacc[j1][2], sacc[j1][3]);
        const uint32_t vbase = (uint32_t)(ks * 16 + bRowV) * AROWB + bColV;
#pragma unroll
        for (int m = 0; m < 4; m++) {
            uint32_t bvh[4];
            LDSM4T(bvh, sb + AS_VH + vbase + m * 32);
            MMA16816(pacc[2*m+0], Pf, bvh[0], bvh[1]);
            MMA16816(pacc[2*m+1], Pf, bvh[2], bvh[3]);
        }
    }

    const size_t rowA = ((size_t)(bb * SEQN) + qbase + ra) * DIM + h * DHD;
    const size_t rowB = ((size_t)(bb * SEQN) + qbase + rb) * DIM + h * DHD;
#pragma unroll
    for (int nt = 0; nt < 8; nt++) {
        const int d = nt * 8 + (lane & 3) * 2;
        *(__half2*)(Ch + rowA + d) = __halves2half2(
            __float2half_rn(pacc[nt][0]), __float2half_rn(pacc[nt][1]));
        *(__half2*)(Ch + rowB + d) = __halves2half2(
            __float2half_rn(pacc[nt][2]), __float2half_rn(pacc[nt][3]));
    }
}

// ===========================================================================
extern "C" void kernel_launch(void* const* d_in, const int* in_sizes, int n_in,
                              void* d_out, int out_size)
{
    (void)in_sizes; (void)n_in; (void)out_size;
    const float* query = (const float*)d_in[0];
    const float* Wq = (const float*)d_in[1];  const float* bq = (const float*)d_in[2];
    const float* Wk = (const float*)d_in[3];  const float* bk = (const float*)d_in[4];
    const float* Wv = (const float*)d_in[5];  const float* bv = (const float*)d_in[6];
    const float* Wo = (const float*)d_in[7];  const float* bo = (const float*)d_in[8];
    const float* gl = (const float*)d_in[9];  const float* bl = (const float*)d_in[10];
    const float* gs = (const float*)d_in[11]; const float* bs = (const float*)d_in[12];
    const float* Wd = (const float*)d_in[13]; const float* bd = (const float*)d_in[14];
    float* out = (float*)d_out;

    float *pKcP,*pVcP;
    __half *pD,*pTmp,*pTv,*pXh,*pCh,*pWth,*pQh,*pQl;
    __half *pKhF,*pVhF,*pPh,*pKch,*pVch;
    cudaGetSymbolAddress((void**)&pTmp, g_tmp);
    cudaGetSymbolAddress((void**)&pTv, g_tv);
    cudaGetSymbolAddress((void**)&pD, g_D);
    cudaGetSymbolAddress((void**)&pKcP, g_KcP);
    cudaGetSymbolAddress((void**)&pVcP, g_VcP);
    cudaGetSymbolAddress((void**)&pXh, g_Xh);
    cudaGetSymbolAddress((void**)&pCh, g_Ch);
    cudaGetSymbolAddress((void**)&pWth, g_Wth);
    cudaGetSymbolAddress((void**)&pQh, g_Qh);
    cudaGetSymbolAddress((void**)&pQl, g_Ql);
    cudaGetSymbolAddress((void**)&pKhF, g_KhF);
    cudaGetSymbolAddress((void**)&pVhF, g_VhF);
    cudaGetSymbolAddress((void**)&pPh, g_Ph);
    cudaGetSymbolAddress((void**)&pKch, g_Kch);
    cudaGetSymbolAddress((void**)&pVch, g_Vch);

    cudaFuncSetAttribute(hgemm_qkvd, cudaFuncAttributeMaxDynamicSharedMemorySize, GEMM_SMEM1);
    cudaFuncSetAttribute(hgemm_o, cudaFuncAttributeMaxDynamicSharedMemorySize, GEMM_SMEM1);
    cudaFuncSetAttribute(compress_hmma, cudaFuncAttributeMaxDynamicSharedMemorySize, COMP_SMEM);
    cudaFuncSetAttribute(attn_hmma, cudaFuncAttributeMaxDynamicSharedMemorySize, ATTN_SMEM);

    split_perm_kernel<<<MROWS * DIM / 4 / 256, 256>>>(query, pXh);
    wsplit_all_kernel<<<dim3(DIM / 32, DIM / 32, 5), dim3(32, 8)>>>(
        Wq, Wk, Wv, Wd, Wo, pWth);

    hgemm_qkvd<<<dim3((3 * DIM + NH * NL) / 128, MROWS / 128), 256, GEMM_SMEM1>>>(
        pXh, pWth, bq, bk, bv, bd, pQh, pQl, pTmp, pTv, pD);

    ln_split2_kernel<<<dim3(MROWS, 2), 256>>>(pTmp, pTv, gl, bl, pKhF, pVhF);

    softmax_col_kernel<<<dim3((NH * NL) / 32, BATCH), 256>>>(pD, pPh);

    compress_hmma<<<dim3(BATCH * NH, NSPLIT), 256, COMP_SMEM>>>(
        pPh, pKhF, pVhF, pKcP, pVcP);
    compress_ln_kernel<<<dim3(BATCH * NL, 2), 256>>>(pKcP, pVcP, gs, bs, pKch, pVch);

    attn_hmma<<<dim3(SEQN / 64, NH, BATCH), 128, ATTN_SMEM>>>(
        pQh, pQl, pKhF, pVhF, pKch, pVch, pCh);

    hgemm_o<<<dim3(DIM / 128, MROWS / 128), 256, GEMM_SMEM1>>>(
        pCh, pWth + WOFF_O, bo, out);
}

// round 16
// speedup vs baseline: 1.0572x; 1.0572x over previous
#include <cuda_runtime.h>
#include <cuda_fp16.h>
#include <math.h>
#include <stdint.h>

#define SEQN  4096
#define BATCH 4
#define DIM   1024
#define NH    16
#define DHD   64
#define NL    32
#define WW    8
#define EE    4
#define BAND  16
#define NG    (SEQN / WW)
#define MROWS (BATCH * SEQN)
#define NSPLIT 8
#define CSIZE (BATCH * NH * NL * DHD)

__device__ float g_KcP[NSPLIT * CSIZE];
__device__ float g_VcP[NSPLIT * CSIZE];

__device__ __align__(16) __half g_D  [BATCH * SEQN * NH * NL];  // logits fp16
__device__ __align__(16) __half g_tmp[BATCH * SEQN * DIM];      // K pre-LN
__device__ __align__(16) __half g_tv [BATCH * SEQN * DIM];      // V pre-LN
__device__ __align__(16) __half g_Xh[MROWS * DIM];
__device__ __align__(16) __half g_Ch[MROWS * DIM];
__device__ __align__(16) __half g_Qh[BATCH * NH * SEQN * DHD];
__device__ __align__(16) __half g_Ql[BATCH * NH * SEQN * DHD];
__device__ __align__(16) __half g_KhF[BATCH * NH * SEQN * DHD];
__device__ __align__(16) __half g_VhF[BATCH * NH * SEQN * DHD];
__device__ __align__(16) __half g_Ph [BATCH * NH * NL * SEQN];  // transposed logits -> probs
__device__ __align__(16) __half g_Kch[CSIZE];
__device__ __align__(16) __half g_Vch[CSIZE];
// weight rows: Q 0-1023, K 1024-2047, V 2048-3071, D 3072-3583, O 3584-4607
#define WOFF_O (3 * DIM * DIM + (NH * NL) * DIM)
#define WT_TOTAL (4 * DIM * DIM + (NH * NL) * DIM)
__device__ __align__(16) __half g_Wth[WT_TOTAL];

// =========================== common asm helpers ============================
__device__ __forceinline__ uint32_t smem_u32(const void* p) {
    uint32_t a;
    asm("{ .reg .u64 t; cvta.to.shared.u64 t, %1; cvt.u32.u64 %0, t; }" : "=r"(a) : "l"(p));
    return a;
}
#define CPA(dst, src) \
    asm volatile("cp.async.cg.shared.global [%0], [%1], 16;" :: "r"(dst), "l"(src))
#define CP_COMMIT() asm volatile("cp.async.commit_group;")
#define CP_WAIT(n)  asm volatile("cp.async.wait_group %0;" :: "n"(n))
#define LDSM4(R, addr) \
    asm volatile("ldmatrix.sync.aligned.m8n8.x4.shared.b16 {%0,%1,%2,%3}, [%4];" \
        : "=r"((R)[0]), "=r"((R)[1]), "=r"((R)[2]), "=r"((R)[3]) : "r"(addr))
#define LDSM4T(R, addr) \
    asm volatile("ldmatrix.sync.aligned.m8n8.x4.trans.shared.b16 {%0,%1,%2,%3}, [%4];" \
        : "=r"((R)[0]), "=r"((R)[1]), "=r"((R)[2]), "=r"((R)[3]) : "r"(addr))
#define MMA16816(d, a, b0, b1) \
    asm volatile("mma.sync.aligned.m16n8k16.row.col.f32.f16.f16.f32 " \
        "{%0,%1,%2,%3}, {%4,%5,%6,%7}, {%8,%9}, {%0,%1,%2,%3};" \
        : "+f"((d)[0]), "+f"((d)[1]), "+f"((d)[2]), "+f"((d)[3]) \
        : "r"((a)[0]), "r"((a)[1]), "r"((a)[2]), "r"((a)[3]), "r"(b0), "r"(b1))

__device__ __forceinline__ uint32_t pack_h2(float lo, float hi) {
    __half2 h = __halves2half2(__float2half_rn(lo), __float2half_rn(hi));
    return *(uint32_t*)&h;
}

// =========================== HMMA GEMM core ================================
#define SROWB 80
#define TILEB (128 * SROWB)
#define NIT (DIM / 32)

template <int TERMS>
__device__ __forceinline__ void hgemm_main(
    const __half* Ah, const __half* Al, const __half* Bh,
    int bm, int bn, uint32_t sb, int tid, float acc[2][8][4])
{
    constexpr uint32_t STG = (TERMS + 1) * TILEB;
    constexpr uint32_t oAH = 0;
    constexpr uint32_t oAL = TILEB;
    constexpr uint32_t oBH = (TERMS >= 2) ? 2 * TILEB : TILEB;

    const int lane = tid & 31, wid = tid >> 5;
    const int wm = wid & 3, wn = wid >> 2;
    const int lr0 = tid >> 2;
    const size_t aoff0 = ((size_t)(bm + lr0) << 10) + (size_t)(tid & 3) * 8;
    const size_t aoff1 = aoff0 + ((size_t)64 << 10);
    const size_t boff0 = ((size_t)(bn + lr0) << 10) + (size_t)(tid & 3) * 8;
    const size_t boff1 = boff0 + ((size_t)64 << 10);
    const uint32_t d0 = (uint32_t)lr0 * SROWB + (tid & 3) * 16;
    const uint32_t d1 = d0 + 64 * SROWB;

    CPA(sb + oAH + d0, Ah + aoff0); CPA(sb + oAH + d1, Ah + aoff1);
    if (TERMS >= 2) { CPA(sb + oAL + d0, Al + aoff0); CPA(sb + oAL + d1, Al + aoff1); }
    CPA(sb + oBH + d0, Bh + boff0); CPA(sb + oBH + d1, Bh + boff1);
    CP_COMMIT();

#pragma unroll
    for (int i = 0; i < 2; i++)
#pragma unroll
        for (int j = 0; j < 8; j++)
#pragma unroll
            for (int k = 0; k < 4; k++) acc[i][j][k] = 0.f;

    const uint32_t aBase = (uint32_t)(wm * 32 + (lane & 15)) * SROWB + (lane >> 4) * 16;
    const uint32_t bBase = (uint32_t)(wn * 64 + ((lane >> 4) & 1) * 8 + (lane & 7)) * SROWB
                           + ((lane >> 3) & 1) * 16;

    for (int it = 0; it < NIT; it++) {
        const uint32_t ps = (it & 1) * STG;
        if (it + 1 < NIT) {
            const uint32_t ns = ((it + 1) & 1) * STG;
            const int kb = (it + 1) * 32;
            CPA(sb + ns + oAH + d0, Ah + aoff0 + kb); CPA(sb + ns + oAH + d1, Ah + aoff1 + kb);
            if (TERMS >= 2) {
                CPA(sb + ns + oAL + d0, Al + aoff0 + kb); CPA(sb + ns + oAL + d1, Al + aoff1 + kb);
            }
            CPA(sb + ns + oBH + d0, Bh + boff0 + kb); CPA(sb + ns + oBH + d1, Bh + boff1 + kb);
            CP_COMMIT();
            CP_WAIT(1);
        } else {
            CP_WAIT(0);
        }
        __syncthreads();

        const uint32_t sAH = sb + ps + oAH + aBase;
        const uint32_t sAL = sb + ps + oAL + aBase;
        const uint32_t sBH = sb + ps + oBH + bBase;
#pragma unroll
        for (int ks = 0; ks < 2; ks++) {
            const uint32_t ko = ks * 32;
            uint32_t ah[2][4], al[2][4];
            LDSM4(ah[0], sAH + ko);
            LDSM4(ah[1], sAH + ko + 16 * SROWB);
            if (TERMS >= 2) {
                LDSM4(al[0], sAL + ko);
                LDSM4(al[1], sAL + ko + 16 * SROWB);
            }
#pragma unroll
            for (int q = 0; q < 4; q++) {
                uint32_t bh[4];
                LDSM4(bh, sBH + ko + q * 16 * SROWB);
#pragma unroll
                for (int mt = 0; mt < 2; mt++) {
                    MMA16816(acc[mt][2 * q + 0], ah[mt], bh[0], bh[1]);
                    MMA16816(acc[mt][2 * q + 1], ah[mt], bh[2], bh[3]);
                    if (TERMS >= 2) {
                        MMA16816(acc[mt][2 * q + 0], al[mt], bh[0], bh[1]);
                        MMA16816(acc[mt][2 * q + 1], al[mt], bh[2], bh[3]);
                    }
                }
            }
        }
        __syncthreads();
    }
}
#define GEMM_SMEM1 (2 * 2 * TILEB)

// ---- fused Q/K/V/D GEMM (1-term); Q fp16 hi/lo, K/V/D fp16 ----
__global__ __launch_bounds__(256, 2) void hgemm_qkvd(
    const __half* __restrict__ Ah, const __half* __restrict__ Bh,
    const float* __restrict__ bq, const float* __restrict__ bk,
    const float* __restrict__ bv, const float* __restrict__ bd,
    __half* __restrict__ outQh, __half* __restrict__ outQl,
    __half* __restrict__ outK, __half* __restrict__ outV, __half* __restrict__ outD)
{
    extern __shared__ __align__(16) char smem[];
    const uint32_t sb = smem_u32(smem);
    const int tid = threadIdx.x, wid = tid >> 5, lane = tid & 31;
    const int bn = blockIdx.x * 128, bm = blockIdx.y * 128;
    float acc[2][8][4];
    hgemm_main<1>(Ah, nullptr, Bh, bm, bn, sb, tid, acc);

    const int seg = bn >> 10;
    const int cl = bn & 1023;
    const float* bias = seg == 0 ? bq : seg == 1 ? bk : seg == 2 ? bv : bd;
    const float scale = seg == 0 ? 0.125f : 1.f;
    const int wm = wid & 3, wn = wid >> 2;
    const int r0 = bm + wm * 32 + (lane >> 2);
    const int c0 = cl + wn * 64 + (lane & 3) * 2;
#pragma unroll
    for (int mt = 0; mt < 2; mt++) {
#pragma unroll
        for (int hf = 0; hf < 2; hf++) {
            const int r = r0 + mt * 16 + hf * 8;
            const int bb = r >> 12, ss = r & (SEQN - 1);
#pragma unroll
            for (int nt = 0; nt < 8; nt++) {
                const int col = c0 + nt * 8;
                const float2 bv2 = *(const float2*)(bias + col);
                float vx = (acc[mt][nt][hf * 2 + 0] + bv2.x) * scale;
                float vy = (acc[mt][nt][hf * 2 + 1] + bv2.y) * scale;
                if (seg == 0) {
                    size_t o = ((size_t)(bb * NH + (col >> 6)) * SEQN + ss) * DHD + (col & 63);
                    __half hx = __float2half_rn(vx), hy = __float2half_rn(vy);
                    *(__half2*)(outQh + o) = __halves2half2(hx, hy);
                    *(__half2*)(outQl + o) = __halves2half2(
                        __float2half_rn(vx - __half2float(hx)),
                        __float2half_rn(vy - __half2float(hy)));
                } else if (seg == 3) {
                    *(__half2*)(outD + (size_t)r * (NH * NL) + col) =
                        __halves2half2(__float2half_rn(vx), __float2half_rn(vy));
                } else {
                    __half* op = (seg == 1) ? outK : outV;
                    *(__half2*)(op + (size_t)r * DIM + col) =
                        __halves2half2(__float2half_rn(vx), __float2half_rn(vy));
                }
            }
        }
    }
}

// ---- output GEMM (1-term): out = C @ Wo + bo, (s,b,DIM) ----
__global__ __launch_bounds__(256, 2) void hgemm_o(
    const __half* __restrict__ Ah, const __half* __restrict__ Bh,
    const float* __restrict__ bias, float* __restrict__ out)
{
    extern __shared__ __align__(16) char smem[];
    const uint32_t sb = smem_u32(smem);
    const int tid = threadIdx.x, wid = tid >> 5, lane = tid & 31;
    const int bn = blockIdx.x * 128, bm = blockIdx.y * 128;
    float acc[2][8][4];
    hgemm_main<1>(Ah, nullptr, Bh, bm, bn, sb, tid, acc);

    const int wm = wid & 3, wn = wid >> 2;
    const int r0 = bm + wm * 32 + (lane >> 2);
    const int c0 = bn + wn * 64 + (lane & 3) * 2;
#pragma unroll
    for (int mt = 0; mt < 2; mt++) {
#pragma unroll
        for (int hf = 0; hf < 2; hf++) {
            const int r = r0 + mt * 16 + hf * 8;
            const int bb = r >> 12, ss = r & (SEQN - 1);
#pragma unroll
            for (int nt = 0; nt < 8; nt++) {
                const int col = c0 + nt * 8;
                const float2 bv2 = *(const float2*)(bias + col);
                *(float2*)(out + ((size_t)ss * BATCH + bb) * DIM + col) =
                    make_float2(acc[mt][nt][hf * 2 + 0] + bv2.x,
                                acc[mt][nt][hf * 2 + 1] + bv2.y);
            }
        }
    }
}

// ================= HMMA compress: Kc/Vc partials (1-term) ==================
#define CPROW 144
#define CPS_PH 0
#define CPS_K  (32 * CPROW)
#define CPS_V  (96 * CPROW)
#define CP_STG (160 * CPROW)
#define COMP_SMEM (2 * CP_STG)

__global__ __launch_bounds__(256, 2) void compress_hmma(
    const __half* __restrict__ Ph,
    const __half* __restrict__ Kh, const __half* __restrict__ Vh,
    float* __restrict__ partK, float* __restrict__ partV)
{
    extern __shared__ __align__(16) char smem[];
    const uint32_t sb = smem_u32(smem);
    const int bh = blockIdx.x, sp = blockIdx.y;
    const int b = bh >> 4, h = bh & 15;
    const int tid = threadIdx.x, lane = tid & 31, wid = tid >> 5;

    const size_t pbase = ((size_t)(b * (NH * NL) + h * NL)) * SEQN + sp * 512;
    const size_t kbase = ((size_t)bh * SEQN + sp * 512) * DHD;

    const int prow = tid >> 3, pseg = tid & 7;
    const uint32_t pDst = prow * CPROW + pseg * 16;
    const size_t pSrc = (size_t)prow * SEQN + pseg * 8;
    const uint32_t kDst0 = prow * CPROW + pseg * 16;
    const uint32_t kDst1 = (prow + 32) * CPROW + pseg * 16;
    const size_t kSrc0 = (size_t)prow * DHD + pseg * 8;
    const size_t kSrc1 = (size_t)(prow + 32) * DHD + pseg * 8;

    CPA(sb + CPS_PH + pDst, Ph + pbase + pSrc);
    CPA(sb + CPS_K + kDst0, Kh + kbase + kSrc0);
    CPA(sb + CPS_K + kDst1, Kh + kbase + kSrc1);
    CPA(sb + CPS_V + kDst0, Vh + kbase + kSrc0);
    CPA(sb + CPS_V + kDst1, Vh + kbase + kSrc1);
    CP_COMMIT();

    float acc[4][4];
#pragma unroll
    for (int i = 0; i < 4; i++)
#pragma unroll
        for (int j = 0; j < 4; j++) acc[i][j] = 0.f;

    const int outv = wid >> 2;
    const int mt = wid & 1, nh2 = (wid >> 1) & 1;
    const uint32_t aOff = (uint32_t)(mt * 16 + (lane & 15)) * CPROW + (lane >> 4) * 16;
    const uint32_t bRow = (lane & 7) + ((lane >> 3) & 1) * 8;
    const uint32_t bCol = ((lane >> 4) & 1) * 16 + nh2 * 64;
    const uint32_t kvOff = outv ? CPS_V : CPS_K;

    for (int c = 0; c < 8; c++) {
        const uint32_t ps = (c & 1) * CP_STG;
        if (c + 1 < 8) {
            const uint32_t ns = ((c + 1) & 1) * CP_STG;
            const int so = (c + 1) * 64;
            CPA(sb + ns + CPS_PH + pDst, Ph + pbase + so + pSrc);
            CPA(sb + ns + CPS_K + kDst0, Kh + kbase + (size_t)so * DHD + kSrc0);
            CPA(sb + ns + CPS_K + kDst1, Kh + kbase + (size_t)so * DHD + kSrc1);
            CPA(sb + ns + CPS_V + kDst0, Vh + kbase + (size_t)so * DHD + kSrc0);
            CPA(sb + ns + CPS_V + kDst1, Vh + kbase + (size_t)so * DHD + kSrc1);
            CP_COMMIT();
            CP_WAIT(1);
        } else {
            CP_WAIT(0);
        }
        __syncthreads();

        const uint32_t sP0 = sb + ps + CPS_PH + aOff;
        const uint32_t sKV = sb + ps + kvOff;
#pragma unroll
        for (int ks = 0; ks < 4; ks++) {
            uint32_t ah[4], b0[4], b1[4];
            LDSM4(ah, sP0 + ks * 32);
            const uint32_t ba = sKV + (ks * 16 + bRow) * CPROW + bCol;
            LDSM4T(b0, ba);
            LDSM4T(b1, ba + 32);
            MMA16816(acc[0], ah, b0[0], b0[1]);
            MMA16816(acc[1], ah, b0[2], b0[3]);
            MMA16816(acc[2], ah, b1[0], b1[1]);
            MMA16816(acc[3], ah, b1[2], b1[3]);
        }
        __syncthreads();
    }

    float* outp = outv ? partV : partK;
    const size_t ob = (size_t)sp * CSIZE + (size_t)bh * NL * DHD;
    const int l0 = mt * 16 + (lane >> 2);
    const int db = nh2 * 32 + (lane & 3) * 2;
#pragma unroll
    for (int nt = 0; nt < 4; nt++) {
        const int d = db + nt * 8;
        *(float2*)(outp + ob + (size_t)l0 * DHD + d) = make_float2(acc[nt][0], acc[nt][1]);
        *(float2*)(outp + ob + (size_t)(l0 + 8) * DHD + d) = make_float2(acc[nt][2], acc[nt][3]);
    }
}

// ---- fp32 -> fp16 with (s,b)->(b,s) permute ----
__global__ __launch_bounds__(256) void split_perm_kernel(
    const float* __restrict__ X, __half* __restrict__ H)
{
    int i = blockIdx.x * 256 + threadIdx.x;
    int r = i >> 8, k4 = i & 255;
    int b = r >> 12, s = r & (SEQN - 1);
    float4 v = *((const float4*)X + ((size_t)s * BATCH + b) * 256 + k4);
    __half2* Hp = (__half2*)(H + (size_t)i * 4);
    Hp[0] = __halves2half2(__float2half_rn(v.x), __float2half_rn(v.y));
    Hp[1] = __halves2half2(__float2half_rn(v.z), __float2half_rn(v.w));
}

// ---- all 5 weight transposes (fp16) in one launch ----
__global__ void wsplit_all_kernel(
    const float* __restrict__ Wq, const float* __restrict__ Wk,
    const float* __restrict__ Wv, const float* __restrict__ Wd,
    const float* __restrict__ Wo, __half* __restrict__ Th)
{
    __shared__ float t[32][33];
    int z = blockIdx.z;
    int N = (z == 3) ? (NH * NL) : DIM;
    if (blockIdx.x * 32 >= N) return;
    const float* W = z == 0 ? Wq : z == 1 ? Wk : z == 2 ? Wv : z == 3 ? Wd : Wo;
    size_t woff = z <= 3 ? (size_t)z * DIM * DIM : (size_t)WOFF_O;
    int n0 = blockIdx.x * 32, k0 = blockIdx.y * 32;
    int x = threadIdx.x, y = threadIdx.y;
#pragma unroll
    for (int i = 0; i < 32; i += 8)
        t[y + i][x] = W[(size_t)(k0 + y + i) * N + n0 + x];
    __syncthreads();
#pragma unroll
    for (int i = 0; i < 32; i += 8)
        Th[woff + (size_t)(n0 + y + i) * DIM + k0 + x] = __float2half_rn(t[x][y + i]);
}

// ---- LayerNorm over DIM (fp16 in), head-split; fp16 out ----
__global__ __launch_bounds__(256) void ln_split2_kernel(
    const __half* __restrict__ XK, const __half* __restrict__ XV,
    const float* __restrict__ gamma, const float* __restrict__ beta,
    __half* __restrict__ oKh, __half* __restrict__ oVh)
{
    __shared__ float shs[8], shq[8];
    int r = blockIdx.x, tid = threadIdx.x;
    const __half* X = blockIdx.y ? XV : XK;
    __half* outh = blockIdx.y ? oVh : oKh;
    const __half2* xp = (const __half2*)(X + (size_t)r * DIM) + tid * 2;
    float2 a = __half22float2(xp[0]);
    float2 bq2 = __half22float2(xp[1]);
    float vx = a.x, vy = a.y, vz = bq2.x, vw = bq2.y;
    float s = vx + vy + vz + vw;
    float q = vx*vx + vy*vy + vz*vz + vw*vw;
    int lane = tid & 31, wid = tid >> 5;
#pragma unroll
    for (int o = 16; o; o >>= 1) {
        s += __shfl_xor_sync(~0u, s, o); q += __shfl_xor_sync(~0u, q, o);
    }
    if (lane == 0) { shs[wid] = s; shq[wid] = q; }
    __syncthreads();
    if (tid == 0) {
        float ts = 0, tq = 0;
        for (int i = 0; i < 8; i++) { ts += shs[i]; tq += shq[i]; }
        shs[0] = ts; shq[0] = tq;
    }
    __syncthreads();
    float mean = shs[0] * (1.f / DIM);
    float rstd = rsqrtf(shq[0] * (1.f / DIM) - mean * mean + 1e-5f);
    int c = tid * 4;
    float4 g4 = ((const float4*)gamma)[tid], b4 = ((const float4*)beta)[tid];
    float o0 = (vx - mean) * rstd * g4.x + b4.x;
    float o1 = (vy - mean) * rstd * g4.y + b4.y;
    float o2 = (vz - mean) * rstd * g4.z + b4.z;
    float o3 = (vw - mean) * rstd * g4.w + b4.w;
    int b = r >> 12, sq = r & (SEQN - 1);
    size_t base = ((size_t)(b * NH + (c >> 6)) * SEQN + sq) * DHD + (c & 63);
    __half2* hp = (__half2*)(outh + base);
    hp[0] = __halves2half2(__float2half_rn(o0), __float2half_rn(o1));
    hp[1] = __halves2half2(__float2half_rn(o2), __float2half_rn(o3));
}

// ---- transpose (b,s,512) fp16 -> (b,512,s) fp16 ----
__global__ void transpose_h_kernel(const __half* __restrict__ D, __half* __restrict__ P)
{
    __shared__ __half t[32][36];
    int b = blockIdx.z, c0 = blockIdx.x * 32, s0 = blockIdx.y * 32;
    int x = threadIdx.x, y = threadIdx.y;
    const __half* Db = D + (size_t)b * SEQN * (NH * NL);
    __half* Pb = P + (size_t)b * (NH * NL) * SEQN;
#pragma unroll
    for (int i = 0; i < 32; i += 8)
        t[y + i][x] = Db[(size_t)(s0 + y + i) * (NH * NL) + c0 + x];
    __syncthreads();
#pragma unroll
    for (int i = 0; i < 32; i += 8)
        Pb[(size_t)(c0 + y + i) * SEQN + s0 + x] = t[x][y + i];
}

// ---- row softmax over 4096, fp16 in-place ----
__global__ __launch_bounds__(256) void softmax_rows_h_kernel(__half* __restrict__ P)
{
    __shared__ float sh[8];
    size_t base = (size_t)blockIdx.x * SEQN;
    int tid = threadIdx.x, lane = tid & 31, wid = tid >> 5;
    float v[16], m = -1e30f;
#pragma unroll
    for (int i = 0; i < 16; i++) {
        v[i] = __half2float(P[base + tid + i * 256]);
        m = fmaxf(m, v[i]);
    }
#pragma unroll
    for (int o = 16; o; o >>= 1) m = fmaxf(m, __shfl_xor_sync(~0u, m, o));
    if (lane == 0) sh[wid] = m;
    __syncthreads();
    if (tid == 0) { float t = sh[0]; for (int i = 1; i < 8; i++) t = fmaxf(t, sh[i]); sh[0] = t; }
    __syncthreads();
    float M = sh[0];
    __syncthreads();
    float s = 0.f;
#pragma unroll
    for (int i = 0; i < 16; i++) { v[i] = __expf(v[i] - M); s += v[i]; }
#pragma unroll
    for (int o = 16; o; o >>= 1) s += __shfl_xor_sync(~0u, s, o);
    if (lane == 0) sh[wid] = s;
    __syncthreads();
    if (tid == 0) { float t = 0; for (int i = 0; i < 8; i++) t += sh[i]; sh[0] = t; }
    __syncthreads();
    float inv = 1.f / sh[0];
#pragma unroll
    for (int i = 0; i < 16; i++)
        P[base + tid + i * 256] = __float2half_rn(v[i] * inv);
}

// ---- reduce partials + LN for Kc/Vc; fp16 hi outputs only ----
__global__ __launch_bounds__(256) void compress_ln_kernel(
    const float* __restrict__ partK, const float* __restrict__ partV,
    const float* __restrict__ gamma, const float* __restrict__ beta,
    __half* __restrict__ oKh, __half* __restrict__ oVh)
{
    __shared__ float shs[8], shq[8];
    int bl = blockIdx.x, b = bl >> 5, l = bl & 31;
    const float* part = blockIdx.y ? partV : partK;
    __half* outh = blockIdx.y ? oVh : oKh;
    int tid = threadIdx.x, c = tid * 4;
    size_t base = ((size_t)(b * NH + (c >> 6)) * NL + l) * DHD + (c & 63);
    float4 acc = make_float4(0, 0, 0, 0);
#pragma unroll
    for (int sp = 0; sp < NSPLIT; sp++) {
        float4 p = *(const float4*)(part + (size_t)sp * CSIZE + base);
        acc.x += p.x; acc.y += p.y; acc.z += p.z; acc.w += p.w;
    }
    float s = acc.x + acc.y + acc.z + acc.w;
    float q = acc.x*acc.x + acc.y*acc.y + acc.z*acc.z + acc.w*acc.w;
    int lane = tid & 31, wid = tid >> 5;
#pragma unroll
    for (int o = 16; o; o >>= 1) {
        s += __shfl_xor_sync(~0u, s, o); q += __shfl_xor_sync(~0u, q, o);
    }
    if (lane == 0) { shs[wid] = s; shq[wid] = q; }
    __syncthreads();
    if (tid == 0) {
        float ts = 0, tq = 0;
        for (int i = 0; i < 8; i++) { ts += shs[i]; tq += shq[i]; }
        shs[0] = ts; shq[0] = tq;
    }
    __syncthreads();
    float mean = shs[0] * (1.f / DIM);
    float rstd = rsqrtf(shq[0] * (1.f / DIM) - mean * mean + 1e-5f);
    float4 g4 = ((const float4*)gamma)[tid], b4 = ((const float4*)beta)[tid];
    __half2* hp = (__half2*)(outh + base);
    hp[0] = __halves2half2(__float2half_rn((acc.x - mean) * rstd * g4.x + b4.x),
                           __float2half_rn((acc.y - mean) * rstd * g4.y + b4.y));
    hp[1] = __halves2half2(__float2half_rn((acc.z - mean) * rstd * g4.z + b4.z),
                           __float2half_rn((acc.w - mean) * rstd * g4.w + b4.w));
}

// ================= HMMA attention (QK 2-term, PV 1-term) ===================
#define AROWB 144
#define AS_QH 0
#define AS_QL (64 * AROWB)
#define AS_KH (128 * AROWB)
#define AS_VH (240 * AROWB)
#define ATTN_SMEM (352 * AROWB)    // 50688 B

__global__ __launch_bounds__(128, 3) void attn_hmma(
    const __half* __restrict__ Qh, const __half* __restrict__ Ql,
    const __half* __restrict__ Kh, const __half* __restrict__ Vh,
    const __half* __restrict__ Kch, const __half* __restrict__ Vch,
    __half* __restrict__ Ch)
{
    extern __shared__ __align__(16) char smem[];
    const uint32_t sb = smem_u32(smem);
    const int h = blockIdx.y, bb = blockIdx.z;
    const int bh = bb * NH + h;
    const int qbase = blockIdx.x * 64;
    const int tid = threadIdx.x, lane = tid & 31, warp = tid >> 5;

    for (int idx = tid; idx < 112 * 8; idx += 128) {
        const int row = idx >> 3, seg = idx & 7;
        const uint32_t dst = row * AROWB + seg * 16;
        uint4 kh4 = {0,0,0,0}, vh4 = {0,0,0,0};
        if (row < 32) {
            size_t src = ((size_t)bh * NL + row) * DHD + seg * 8;
            kh4 = *(const uint4*)(Kch + src);
            vh4 = *(const uint4*)(Vch + src);
        } else {
            const int seq = qbase - EE + (row - 32);
            if (seq >= 0 && seq < SEQN) {
                size_t src = ((size_t)bh * SEQN + seq) * DHD + seg * 8;
                kh4 = *(const uint4*)(Kh + src);
                vh4 = *(const uint4*)(Vh + src);
            }
        }
        *(uint4*)(smem + AS_KH + dst) = kh4;
        *(uint4*)(smem + AS_VH + dst) = vh4;
    }
    for (int idx = tid; idx < 64 * 8; idx += 128) {
        const int row = idx >> 3, seg = idx & 7;
        const uint32_t dst = row * AROWB + seg * 16;
        size_t src = ((size_t)bh * SEQN + qbase + row) * DHD + seg * 8;
        *(uint4*)(smem + AS_QH + dst) = *(const uint4*)(Qh + src);
        *(uint4*)(smem + AS_QL + dst) = *(const uint4*)(Ql + src);
    }
    __syncthreads();

    const int r0 = warp * 16;
    float sacc[14][4];
#pragma unroll
    for (int j = 0; j < 14; j++)
#pragma unroll
        for (int e = 0; e < 4; e++) sacc[j][e] = 0.f;

    const uint32_t aOff = (uint32_t)(r0 + (lane & 15)) * AROWB + (lane >> 4) * 16;
    const uint32_t bOffS = (uint32_t)(((lane >> 4) & 1) * 8 + (lane & 7)) * AROWB
                           + ((lane >> 3) & 1) * 16;
#pragma unroll
    for (int ks = 0; ks < 4; ks++) {
        uint32_t ah[4], al[4];
        LDSM4(ah, sb + AS_QH + aOff + ks * 32);
        LDSM4(al, sb + AS_QL + aOff + ks * 32);
#pragma unroll
        for (int i = 0; i < 7; i++) {
            const uint32_t bo = bOffS + (uint32_t)(i * 16) * AROWB + ks * 32;
            uint32_t bh4[4];
            LDSM4(bh4, sb + AS_KH + bo);
            MMA16816(sacc[2*i+0], ah, bh4[0], bh4[1]);
            MMA16816(sacc[2*i+0], al, bh4[0], bh4[1]);
            MMA16816(sacc[2*i+1], ah, bh4[2], bh4[3]);
            MMA16816(sacc[2*i+1], al, bh4[2], bh4[3]);
        }
    }

    const int ra = r0 + (lane >> 2), rb = ra + 8;
    const int ga = ra >> 3, gb = rb >> 3;
    float mxa = -1e30f, mxb = -1e30f;
    bool vld[14][4];
#pragma unroll
    for (int j = 0; j < 14; j++) {
#pragma unroll
        for (int e = 0; e < 2; e++) {
            const int col = j * 8 + (lane & 3) * 2 + e;
            bool va, vb;
            if (col < 32) { va = true; vb = true; }
            else {
                const int w = col - 32;
                const int seq = qbase - EE + w;
                const bool sv = (seq >= 0) && (seq < SEQN);
                va = sv && (w >= ga * 8) && (w < ga * 8 + BAND);
                vb = sv && (w >= gb * 8) && (w < gb * 8 + BAND);
            }
            vld[j][e] = va; vld[j][2 + e] = vb;
            if (va) mxa = fmaxf(mxa, sacc[j][e]);
            if (vb) mxb = fmaxf(mxb, sacc[j][2 + e]);
        }
    }
#pragma unroll
    for (int o = 1; o <= 2; o <<= 1) {
        mxa = fmaxf(mxa, __shfl_xor_sync(~0u, mxa, o));
        mxb = fmaxf(mxb, __shfl_xor_sync(~0u, mxb, o));
    }
    float sma = 0.f, smb = 0.f;
#pragma unroll
    for (int j = 0; j < 14; j++) {
#pragma unroll
        for (int e = 0; e < 2; e++) {
            float pa = vld[j][e]     ? __expf(sacc[j][e]     - mxa) : 0.f;
            float pb = vld[j][2 + e] ? __expf(sacc[j][2 + e] - mxb) : 0.f;
            sacc[j][e] = pa; sacc[j][2 + e] = pb;
            sma += pa; smb += pb;
        }
    }
#pragma unroll
    for (int o = 1; o <= 2; o <<= 1) {
        sma += __shfl_xor_sync(~0u, sma, o);
        smb += __shfl_xor_sync(~0u, smb, o);
    }
    const float iva = 1.f / sma, ivb = 1.f / smb;
#pragma unroll
    for (int j = 0; j < 14; j++) {
        sacc[j][0] *= iva; sacc[j][1] *= iva;
        sacc[j][2] *= ivb; sacc[j][3] *= ivb;
    }

    float pacc[8][4];
#pragma unroll
    for (int i = 0; i < 8; i++)
#pragma unroll
        for (int e = 0; e < 4; e++) pacc[i][e] = 0.f;

    const uint32_t bRowV = (uint32_t)((lane & 7) + ((lane >> 3) & 1) * 8);
    const uint32_t bColV = ((lane >> 4) & 1) * 16;
#pragma unroll
    for (int ks = 0; ks < 7; ks++) {
        const int j0 = 2 * ks, j1 = 2 * ks + 1;
        uint32_t Pf[4];
        Pf[0] = pack_h2(sacc[j0][0], sacc[j0][1]);
        Pf[1] = pack_h2(sacc[j0][2], sacc[j0][3]);
        Pf[2] = pack_h2(sacc[j1][0], sacc[j1][1]);
        Pf[3] = pack_h2(sacc[j1][2], sacc[j1][3]);
        const uint32_t vbase = (uint32_t)(ks * 16 + bRowV) * AROWB + bColV;
#pragma unroll
        for (int m = 0; m < 4; m++) {
            uint32_t bvh[4];
            LDSM4T(bvh, sb + AS_VH + vbase + m * 32);
            MMA16816(pacc[2*m+0], Pf, bvh[0], bvh[1]);
            MMA16816(pacc[2*m+1], Pf, bvh[2], bvh[3]);
        }
    }

    const size_t rowA = ((size_t)(bb * SEQN) + qbase + ra) * DIM + h * DHD;
    const size_t rowB = ((size_t)(bb * SEQN) + qbase + rb) * DIM + h * DHD;
#pragma unroll
    for (int nt = 0; nt < 8; nt++) {
        const int d = nt * 8 + (lane & 3) * 2;
        *(__half2*)(Ch + rowA + d) = __halves2half2(
            __float2half_rn(pacc[nt][0]), __float2half_rn(pacc[nt][1]));
        *(__half2*)(Ch + rowB + d) = __halves2half2(
            __float2half_rn(pacc[nt][2]), __float2half_rn(pacc[nt][3]));
    }
}

// ===========================================================================
extern "C" void kernel_launch(void* const* d_in, const int* in_sizes, int n_in,
                              void* d_out, int out_size)
{
    (void)in_sizes; (void)n_in; (void)out_size;
    const float* query = (const float*)d_in[0];
    const float* Wq = (const float*)d_in[1];  const float* bq = (const float*)d_in[2];
    const float* Wk = (const float*)d_in[3];  const float* bk = (const float*)d_in[4];
    const float* Wv = (const float*)d_in[5];  const float* bv = (const float*)d_in[6];
    const float* Wo = (const float*)d_in[7];  const float* bo = (const float*)d_in[8];
    const float* gl = (const float*)d_in[9];  const float* bl = (const float*)d_in[10];
    const float* gs = (const float*)d_in[11]; const float* bs = (const float*)d_in[12];
    const float* Wd = (const float*)d_in[13]; const float* bd = (const float*)d_in[14];
    float* out = (float*)d_out;

    float *pKcP,*pVcP;
    __half *pD,*pTmp,*pTv,*pXh,*pCh,*pWth,*pQh,*pQl;
    __half *pKhF,*pVhF,*pPh,*pKch,*pVch;
    cudaGetSymbolAddress((void**)&pTmp, g_tmp);
    cudaGetSymbolAddress((void**)&pTv, g_tv);
    cudaGetSymbolAddress((void**)&pD, g_D);
    cudaGetSymbolAddress((void**)&pKcP, g_KcP);
    cudaGetSymbolAddress((void**)&pVcP, g_VcP);
    cudaGetSymbolAddress((void**)&pXh, g_Xh);
    cudaGetSymbolAddress((void**)&pCh, g_Ch);
    cudaGetSymbolAddress((void**)&pWth, g_Wth);
    cudaGetSymbolAddress((void**)&pQh, g_Qh);
    cudaGetSymbolAddress((void**)&pQl, g_Ql);
    cudaGetSymbolAddress((void**)&pKhF, g_KhF);
    cudaGetSymbolAddress((void**)&pVhF, g_VhF);
    cudaGetSymbolAddress((void**)&pPh, g_Ph);
    cudaGetSymbolAddress((void**)&pKch, g_Kch);
    cudaGetSymbolAddress((void**)&pVch, g_Vch);

    cudaFuncSetAttribute(hgemm_qkvd, cudaFuncAttributeMaxDynamicSharedMemorySize, GEMM_SMEM1);
    cudaFuncSetAttribute(hgemm_o, cudaFuncAttributeMaxDynamicSharedMemorySize, GEMM_SMEM1);
    cudaFuncSetAttribute(compress_hmma, cudaFuncAttributeMaxDynamicSharedMemorySize, COMP_SMEM);
    cudaFuncSetAttribute(attn_hmma, cudaFuncAttributeMaxDynamicSharedMemorySize, ATTN_SMEM);

    split_perm_kernel<<<MROWS * DIM / 4 / 256, 256>>>(query, pXh);
    wsplit_all_kernel<<<dim3(DIM / 32, DIM / 32, 5), dim3(32, 8)>>>(
        Wq, Wk, Wv, Wd, Wo, pWth);

    hgemm_qkvd<<<dim3((3 * DIM + NH * NL) / 128, MROWS / 128), 256, GEMM_SMEM1>>>(
        pXh, pWth, bq, bk, bv, bd, pQh, pQl, pTmp, pTv, pD);

    ln_split2_kernel<<<dim3(MROWS, 2), 256>>>(pTmp, pTv, gl, bl, pKhF, pVhF);

    transpose_h_kernel<<<dim3((NH * NL) / 32, SEQN / 32, BATCH), dim3(32, 8)>>>(pD, pPh);
    softmax_rows_h_kernel<<<BATCH * NH * NL, 256>>>(pPh);

    compress_hmma<<<dim3(BATCH * NH, NSPLIT), 256, COMP_SMEM>>>(
        pPh, pKhF, pVhF, pKcP, pVcP);
    compress_ln_kernel<<<dim3(BATCH * NL, 2), 256>>>(pKcP, pVcP, gs, bs, pKch, pVch);

    attn_hmma<<<dim3(SEQN / 64, NH, BATCH), 128, ATTN_SMEM>>>(
        pQh, pQl, pKhF, pVhF, pKch, pVch, pCh);

    hgemm_o<<<dim3(DIM / 128, MROWS / 128), 256, GEMM_SMEM1>>>(
        pCh, pWth + WOFF_O, bo, out);
}

// round 17
// speedup vs baseline: 1.0929x; 1.0338x over previous
#include <cuda_runtime.h>
#include <cuda_fp16.h>
#include <math.h>
#include <stdint.h>

#define SEQN  4096
#define BATCH 4
#define DIM   1024
#define NH    16
#define DHD   64
#define NL    32
#define WW    8
#define EE    4
#define BAND  16
#define NG    (SEQN / WW)
#define MROWS (BATCH * SEQN)
#define NSPLIT 8
#define CSIZE (BATCH * NH * NL * DHD)

__device__ float g_KcP[NSPLIT * CSIZE];
__device__ float g_VcP[NSPLIT * CSIZE];

__device__ __align__(16) __half g_D  [BATCH * SEQN * NH * NL];
__device__ __align__(16) __half g_tmp[BATCH * SEQN * DIM];
__device__ __align__(16) __half g_tv [BATCH * SEQN * DIM];
__device__ __align__(16) __half g_Xh[MROWS * DIM];
__device__ __align__(16) __half g_Ch[MROWS * DIM];
__device__ __align__(16) __half g_Qh[BATCH * NH * SEQN * DHD];
__device__ __align__(16) __half g_KhF[BATCH * NH * SEQN * DHD];
__device__ __align__(16) __half g_VhF[BATCH * NH * SEQN * DHD];
__device__ __align__(16) __half g_Ph [BATCH * NH * NL * SEQN];
__device__ __align__(16) __half g_Kch[CSIZE];
__device__ __align__(16) __half g_Vch[CSIZE];
// weight rows: Q 0-1023, K 1024-2047, V 2048-3071, D 3072-3583, O 3584-4607
#define WOFF_O (3 * DIM * DIM + (NH * NL) * DIM)
#define WT_TOTAL (4 * DIM * DIM + (NH * NL) * DIM)
__device__ __align__(16) __half g_Wth[WT_TOTAL];

// =========================== common asm helpers ============================
__device__ __forceinline__ uint32_t smem_u32(const void* p) {
    uint32_t a;
    asm("{ .reg .u64 t; cvta.to.shared.u64 t, %1; cvt.u32.u64 %0, t; }" : "=r"(a) : "l"(p));
    return a;
}
#define CPA(dst, src) \
    asm volatile("cp.async.cg.shared.global [%0], [%1], 16;" :: "r"(dst), "l"(src))
#define CP_COMMIT() asm volatile("cp.async.commit_group;")
#define CP_WAIT(n)  asm volatile("cp.async.wait_group %0;" :: "n"(n))
#define LDSM4(R, addr) \
    asm volatile("ldmatrix.sync.aligned.m8n8.x4.shared.b16 {%0,%1,%2,%3}, [%4];" \
        : "=r"((R)[0]), "=r"((R)[1]), "=r"((R)[2]), "=r"((R)[3]) : "r"(addr))
#define LDSM4T(R, addr) \
    asm volatile("ldmatrix.sync.aligned.m8n8.x4.trans.shared.b16 {%0,%1,%2,%3}, [%4];" \
        : "=r"((R)[0]), "=r"((R)[1]), "=r"((R)[2]), "=r"((R)[3]) : "r"(addr))
#define MMA16816(d, a, b0, b1) \
    asm volatile("mma.sync.aligned.m16n8k16.row.col.f32.f16.f16.f32 " \
        "{%0,%1,%2,%3}, {%4,%5,%6,%7}, {%8,%9}, {%0,%1,%2,%3};" \
        : "+f"((d)[0]), "+f"((d)[1]), "+f"((d)[2]), "+f"((d)[3]) \
        : "r"((a)[0]), "r"((a)[1]), "r"((a)[2]), "r"((a)[3]), "r"(b0), "r"(b1))

__device__ __forceinline__ uint32_t pack_h2(float lo, float hi) {
    __half2 h = __halves2half2(__float2half_rn(lo), __float2half_rn(hi));
    return *(uint32_t*)&h;
}

// =========================== HMMA GEMM core ================================
#define SROWB 80
#define TILEB (128 * SROWB)
#define NIT (DIM / 32)

template <int TERMS>
__device__ __forceinline__ void hgemm_main(
    const __half* Ah, const __half* Al, const __half* Bh,
    int bm, int bn, uint32_t sb, int tid, float acc[2][8][4])
{
    constexpr uint32_t STG = (TERMS + 1) * TILEB;
    constexpr uint32_t oAH = 0;
    constexpr uint32_t oAL = TILEB;
    constexpr uint32_t oBH = (TERMS >= 2) ? 2 * TILEB : TILEB;

    const int lane = tid & 31, wid = tid >> 5;
    const int wm = wid & 3, wn = wid >> 2;
    const int lr0 = tid >> 2;
    const size_t aoff0 = ((size_t)(bm + lr0) << 10) + (size_t)(tid & 3) * 8;
    const size_t aoff1 = aoff0 + ((size_t)64 << 10);
    const size_t boff0 = ((size_t)(bn + lr0) << 10) + (size_t)(tid & 3) * 8;
    const size_t boff1 = boff0 + ((size_t)64 << 10);
    const uint32_t d0 = (uint32_t)lr0 * SROWB + (tid & 3) * 16;
    const uint32_t d1 = d0 + 64 * SROWB;

    CPA(sb + oAH + d0, Ah + aoff0); CPA(sb + oAH + d1, Ah + aoff1);
    if (TERMS >= 2) { CPA(sb + oAL + d0, Al + aoff0); CPA(sb + oAL + d1, Al + aoff1); }
    CPA(sb + oBH + d0, Bh + boff0); CPA(sb + oBH + d1, Bh + boff1);
    CP_COMMIT();

#pragma unroll
    for (int i = 0; i < 2; i++)
#pragma unroll
        for (int j = 0; j < 8; j++)
#pragma unroll
            for (int k = 0; k < 4; k++) acc[i][j][k] = 0.f;

    const uint32_t aBase = (uint32_t)(wm * 32 + (lane & 15)) * SROWB + (lane >> 4) * 16;
    const uint32_t bBase = (uint32_t)(wn * 64 + ((lane >> 4) & 1) * 8 + (lane & 7)) * SROWB
                           + ((lane >> 3) & 1) * 16;

    for (int it = 0; it < NIT; it++) {
        const uint32_t ps = (it & 1) * STG;
        if (it + 1 < NIT) {
            const uint32_t ns = ((it + 1) & 1) * STG;
            const int kb = (it + 1) * 32;
            CPA(sb + ns + oAH + d0, Ah + aoff0 + kb); CPA(sb + ns + oAH + d1, Ah + aoff1 + kb);
            if (TERMS >= 2) {
                CPA(sb + ns + oAL + d0, Al + aoff0 + kb); CPA(sb + ns + oAL + d1, Al + aoff1 + kb);
            }
            CPA(sb + ns + oBH + d0, Bh + boff0 + kb); CPA(sb + ns + oBH + d1, Bh + boff1 + kb);
            CP_COMMIT();
            CP_WAIT(1);
        } else {
            CP_WAIT(0);
        }
        __syncthreads();

        const uint32_t sAH = sb + ps + oAH + aBase;
        const uint32_t sAL = sb + ps + oAL + aBase;
        const uint32_t sBH = sb + ps + oBH + bBase;
#pragma unroll
        for (int ks = 0; ks < 2; ks++) {
            const uint32_t ko = ks * 32;
            uint32_t ah[2][4], al[2][4];
            LDSM4(ah[0], sAH + ko);
            LDSM4(ah[1], sAH + ko + 16 * SROWB);
            if (TERMS >= 2) {
                LDSM4(al[0], sAL + ko);
                LDSM4(al[1], sAL + ko + 16 * SROWB);
            }
#pragma unroll
            for (int q = 0; q < 4; q++) {
                uint32_t bh[4];
                LDSM4(bh, sBH + ko + q * 16 * SROWB);
#pragma unroll
                for (int mt = 0; mt < 2; mt++) {
                    MMA16816(acc[mt][2 * q + 0], ah[mt], bh[0], bh[1]);
                    MMA16816(acc[mt][2 * q + 1], ah[mt], bh[2], bh[3]);
                    if (TERMS >= 2) {
                        MMA16816(acc[mt][2 * q + 0], al[mt], bh[0], bh[1]);
                        MMA16816(acc[mt][2 * q + 1], al[mt], bh[2], bh[3]);
                    }
                }
            }
        }
        __syncthreads();
    }
}
#define GEMM_SMEM1 (2 * 2 * TILEB)

// ---- fused Q/K/V/D GEMM (1-term); all outputs fp16 ----
__global__ __launch_bounds__(256, 2) void hgemm_qkvd(
    const __half* __restrict__ Ah, const __half* __restrict__ Bh,
    const float* __restrict__ bq, const float* __restrict__ bk,
    const float* __restrict__ bv, const float* __restrict__ bd,
    __half* __restrict__ outQh,
    __half* __restrict__ outK, __half* __restrict__ outV, __half* __restrict__ outD)
{
    extern __shared__ __align__(16) char smem[];
    const uint32_t sb = smem_u32(smem);
    const int tid = threadIdx.x, wid = tid >> 5, lane = tid & 31;
    const int bn = blockIdx.x * 128, bm = blockIdx.y * 128;
    float acc[2][8][4];
    hgemm_main<1>(Ah, nullptr, Bh, bm, bn, sb, tid, acc);

    const int seg = bn >> 10;
    const int cl = bn & 1023;
    const float* bias = seg == 0 ? bq : seg == 1 ? bk : seg == 2 ? bv : bd;
    const float scale = seg == 0 ? 0.125f : 1.f;
    const int wm = wid & 3, wn = wid >> 2;
    const int r0 = bm + wm * 32 + (lane >> 2);
    const int c0 = cl + wn * 64 + (lane & 3) * 2;
#pragma unroll
    for (int mt = 0; mt < 2; mt++) {
#pragma unroll
        for (int hf = 0; hf < 2; hf++) {
            const int r = r0 + mt * 16 + hf * 8;
            const int bb = r >> 12, ss = r & (SEQN - 1);
#pragma unroll
            for (int nt = 0; nt < 8; nt++) {
                const int col = c0 + nt * 8;
                const float2 bv2 = *(const float2*)(bias + col);
                float vx = (acc[mt][nt][hf * 2 + 0] + bv2.x) * scale;
                float vy = (acc[mt][nt][hf * 2 + 1] + bv2.y) * scale;
                __half2 hv = __halves2half2(__float2half_rn(vx), __float2half_rn(vy));
                if (seg == 0) {
                    size_t o = ((size_t)(bb * NH + (col >> 6)) * SEQN + ss) * DHD + (col & 63);
                    *(__half2*)(outQh + o) = hv;
                } else if (seg == 3) {
                    *(__half2*)(outD + (size_t)r * (NH * NL) + col) = hv;
                } else {
                    __half* op = (seg == 1) ? outK : outV;
                    *(__half2*)(op + (size_t)r * DIM + col) = hv;
                }
            }
        }
    }
}

// ---- output GEMM (1-term): out = C @ Wo + bo, (s,b,DIM) ----
__global__ __launch_bounds__(256, 2) void hgemm_o(
    const __half* __restrict__ Ah, const __half* __restrict__ Bh,
    const float* __restrict__ bias, float* __restrict__ out)
{
    extern __shared__ __align__(16) char smem[];
    const uint32_t sb = smem_u32(smem);
    const int tid = threadIdx.x, wid = tid >> 5, lane = tid & 31;
    const int bn = blockIdx.x * 128, bm = blockIdx.y * 128;
    float acc[2][8][4];
    hgemm_main<1>(Ah, nullptr, Bh, bm, bn, sb, tid, acc);

    const int wm = wid & 3, wn = wid >> 2;
    const int r0 = bm + wm * 32 + (lane >> 2);
    const int c0 = bn + wn * 64 + (lane & 3) * 2;
#pragma unroll
    for (int mt = 0; mt < 2; mt++) {
#pragma unroll
        for (int hf = 0; hf < 2; hf++) {
            const int r = r0 + mt * 16 + hf * 8;
            const int bb = r >> 12, ss = r & (SEQN - 1);
#pragma unroll
            for (int nt = 0; nt < 8; nt++) {
                const int col = c0 + nt * 8;
                const float2 bv2 = *(const float2*)(bias + col);
                *(float2*)(out + ((size_t)ss * BATCH + bb) * DIM + col) =
                    make_float2(acc[mt][nt][hf * 2 + 0] + bv2.x,
                                acc[mt][nt][hf * 2 + 1] + bv2.y);
            }
        }
    }
}

// ================= HMMA compress: Kc/Vc partials (1-term) ==================
#define CPROW 144
#define CPS_PH 0
#define CPS_K  (32 * CPROW)
#define CPS_V  (96 * CPROW)
#define CP_STG (160 * CPROW)
#define COMP_SMEM (2 * CP_STG)

__global__ __launch_bounds__(256, 2) void compress_hmma(
    const __half* __restrict__ Ph,
    const __half* __restrict__ Kh, const __half* __restrict__ Vh,
    float* __restrict__ partK, float* __restrict__ partV)
{
    extern __shared__ __align__(16) char smem[];
    const uint32_t sb = smem_u32(smem);
    const int bh = blockIdx.x, sp = blockIdx.y;
    const int b = bh >> 4, h = bh & 15;
    const int tid = threadIdx.x, lane = tid & 31, wid = tid >> 5;

    const size_t pbase = ((size_t)(b * (NH * NL) + h * NL)) * SEQN + sp * 512;
    const size_t kbase = ((size_t)bh * SEQN + sp * 512) * DHD;

    const int prow = tid >> 3, pseg = tid & 7;
    const uint32_t pDst = prow * CPROW + pseg * 16;
    const size_t pSrc = (size_t)prow * SEQN + pseg * 8;
    const uint32_t kDst0 = prow * CPROW + pseg * 16;
    const uint32_t kDst1 = (prow + 32) * CPROW + pseg * 16;
    const size_t kSrc0 = (size_t)prow * DHD + pseg * 8;
    const size_t kSrc1 = (size_t)(prow + 32) * DHD + pseg * 8;

    CPA(sb + CPS_PH + pDst, Ph + pbase + pSrc);
    CPA(sb + CPS_K + kDst0, Kh + kbase + kSrc0);
    CPA(sb + CPS_K + kDst1, Kh + kbase + kSrc1);
    CPA(sb + CPS_V + kDst0, Vh + kbase + kSrc0);
    CPA(sb + CPS_V + kDst1, Vh + kbase + kSrc1);
    CP_COMMIT();

    float acc[4][4];
#pragma unroll
    for (int i = 0; i < 4; i++)
#pragma unroll
        for (int j = 0; j < 4; j++) acc[i][j] = 0.f;

    const int outv = wid >> 2;
    const int mt = wid & 1, nh2 = (wid >> 1) & 1;
    const uint32_t aOff = (uint32_t)(mt * 16 + (lane & 15)) * CPROW + (lane >> 4) * 16;
    const uint32_t bRow = (lane & 7) + ((lane >> 3) & 1) * 8;
    const uint32_t bCol = ((lane >> 4) & 1) * 16 + nh2 * 64;
    const uint32_t kvOff = outv ? CPS_V : CPS_K;

    for (int c = 0; c < 8; c++) {
        const uint32_t ps = (c & 1) * CP_STG;
        if (c + 1 < 8) {
            const uint32_t ns = ((c + 1) & 1) * CP_STG;
            const int so = (c + 1) * 64;
            CPA(sb + ns + CPS_PH + pDst, Ph + pbase + so + pSrc);
            CPA(sb + ns + CPS_K + kDst0, Kh + kbase + (size_t)so * DHD + kSrc0);
            CPA(sb + ns + CPS_K + kDst1, Kh + kbase + (size_t)so * DHD + kSrc1);
            CPA(sb + ns + CPS_V + kDst0, Vh + kbase + (size_t)so * DHD + kSrc0);
            CPA(sb + ns + CPS_V + kDst1, Vh + kbase + (size_t)so * DHD + kSrc1);
            CP_COMMIT();
            CP_WAIT(1);
        } else {
            CP_WAIT(0);
        }
        __syncthreads();

        const uint32_t sP0 = sb + ps + CPS_PH + aOff;
        const uint32_t sKV = sb + ps + kvOff;
#pragma unroll
        for (int ks = 0; ks < 4; ks++) {
            uint32_t ah[4], b0[4], b1[4];
            LDSM4(ah, sP0 + ks * 32);
            const uint32_t ba = sKV + (ks * 16 + bRow) * CPROW + bCol;
            LDSM4T(b0, ba);
            LDSM4T(b1, ba + 32);
            MMA16816(acc[0], ah, b0[0], b0[1]);
            MMA16816(acc[1], ah, b0[2], b0[3]);
            MMA16816(acc[2], ah, b1[0], b1[1]);
            MMA16816(acc[3], ah, b1[2], b1[3]);
        }
        __syncthreads();
    }

    float* outp = outv ? partV : partK;
    const size_t ob = (size_t)sp * CSIZE + (size_t)bh * NL * DHD;
    const int l0 = mt * 16 + (lane >> 2);
    const int db = nh2 * 32 + (lane & 3) * 2;
#pragma unroll
    for (int nt = 0; nt < 4; nt++) {
        const int d = db + nt * 8;
        *(float2*)(outp + ob + (size_t)l0 * DHD + d) = make_float2(acc[nt][0], acc[nt][1]);
        *(float2*)(outp + ob + (size_t)(l0 + 8) * DHD + d) = make_float2(acc[nt][2], acc[nt][3]);
    }
}

// ---- fp32 -> fp16 with (s,b)->(b,s) permute ----
__global__ __launch_bounds__(256) void split_perm_kernel(
    const float* __restrict__ X, __half* __restrict__ H)
{
    int i = blockIdx.x * 256 + threadIdx.x;
    int r = i >> 8, k4 = i & 255;
    int b = r >> 12, s = r & (SEQN - 1);
    float4 v = *((const float4*)X + ((size_t)s * BATCH + b) * 256 + k4);
    __half2* Hp = (__half2*)(H + (size_t)i * 4);
    Hp[0] = __halves2half2(__float2half_rn(v.x), __float2half_rn(v.y));
    Hp[1] = __halves2half2(__float2half_rn(v.z), __float2half_rn(v.w));
}

// ---- all 5 weight transposes (fp16) in one launch ----
__global__ void wsplit_all_kernel(
    const float* __restrict__ Wq, const float* __restrict__ Wk,
    const float* __restrict__ Wv, const float* __restrict__ Wd,
    const float* __restrict__ Wo, __half* __restrict__ Th)
{
    __shared__ float t[32][33];
    int z = blockIdx.z;
    int N = (z == 3) ? (NH * NL) : DIM;
    if (blockIdx.x * 32 >= N) return;
    const float* W = z == 0 ? Wq : z == 1 ? Wk : z == 2 ? Wv : z == 3 ? Wd : Wo;
    size_t woff = z <= 3 ? (size_t)z * DIM * DIM : (size_t)WOFF_O;
    int n0 = blockIdx.x * 32, k0 = blockIdx.y * 32;
    int x = threadIdx.x, y = threadIdx.y;
#pragma unroll
    for (int i = 0; i < 32; i += 8)
        t[y + i][x] = W[(size_t)(k0 + y + i) * N + n0 + x];
    __syncthreads();
#pragma unroll
    for (int i = 0; i < 32; i += 8)
        Th[woff + (size_t)(n0 + y + i) * DIM + k0 + x] = __float2half_rn(t[x][y + i]);
}

// ---- LayerNorm over DIM (fp16 in), head-split; fp16 out; 128 thr/row ----
__global__ __launch_bounds__(128) void ln_split2_kernel(
    const __half* __restrict__ XK, const __half* __restrict__ XV,
    const float* __restrict__ gamma, const float* __restrict__ beta,
    __half* __restrict__ oKh, __half* __restrict__ oVh)
{
    __shared__ float shs[4], shq[4];
    const int r = blockIdx.x, tid = threadIdx.x;
    const __half* X = blockIdx.y ? XV : XK;
    __half* outh = blockIdx.y ? oVh : oKh;

    uint4 raw = *((const uint4*)(X + (size_t)r * DIM) + tid);
    const __half2* h2 = (const __half2*)&raw;
    float v[8];
#pragma unroll
    for (int i = 0; i < 4; i++) {
        float2 f = __half22float2(h2[i]);
        v[2 * i] = f.x; v[2 * i + 1] = f.y;
    }
    float s = 0.f, q = 0.f;
#pragma unroll
    for (int i = 0; i < 8; i++) { s += v[i]; q += v[i] * v[i]; }
    const int lane = tid & 31, wid = tid >> 5;
#pragma unroll
    for (int o = 16; o; o >>= 1) {
        s += __shfl_xor_sync(~0u, s, o); q += __shfl_xor_sync(~0u, q, o);
    }
    if (lane == 0) { shs[wid] = s; shq[wid] = q; }
    __syncthreads();
    float ts = shs[0] + shs[1] + shs[2] + shs[3];
    float tq = shq[0] + shq[1] + shq[2] + shq[3];
    const float mean = ts * (1.f / DIM);
    const float rstd = rsqrtf(tq * (1.f / DIM) - mean * mean + 1e-5f);

    const int c = tid * 8;
    const float4 g0 = ((const float4*)gamma)[tid * 2];
    const float4 g1 = ((const float4*)gamma)[tid * 2 + 1];
    const float4 b0 = ((const float4*)beta)[tid * 2];
    const float4 b1 = ((const float4*)beta)[tid * 2 + 1];
    const float gg[8] = {g0.x, g0.y, g0.z, g0.w, g1.x, g1.y, g1.z, g1.w};
    const float bb8[8] = {b0.x, b0.y, b0.z, b0.w, b1.x, b1.y, b1.z, b1.w};
    __half2 oh[4];
#pragma unroll
    for (int i = 0; i < 4; i++) {
        float a0 = (v[2 * i] - mean) * rstd * gg[2 * i] + bb8[2 * i];
        float a1 = (v[2 * i + 1] - mean) * rstd * gg[2 * i + 1] + bb8[2 * i + 1];
        oh[i] = __halves2half2(__float2half_rn(a0), __float2half_rn(a1));
    }
    const int b = r >> 12, sq = r & (SEQN - 1);
    size_t base = ((size_t)(b * NH + (c >> 6)) * SEQN + sq) * DHD + (c & 63);
    *(uint4*)(outh + base) = *(uint4*)oh;
}

// ---- transpose (b,s,512) fp16 -> (b,512,s) fp16 ----
__global__ void transpose_h_kernel(const __half* __restrict__ D, __half* __restrict__ P)
{
    __shared__ __half t[32][36];
    int b = blockIdx.z, c0 = blockIdx.x * 32, s0 = blockIdx.y * 32;
    int x = threadIdx.x, y = threadIdx.y;
    const __half* Db = D + (size_t)b * SEQN * (NH * NL);
    __half* Pb = P + (size_t)b * (NH * NL) * SEQN;
#pragma unroll
    for (int i = 0; i < 32; i += 8)
        t[y + i][x] = Db[(size_t)(s0 + y + i) * (NH * NL) + c0 + x];
    __syncthreads();
#pragma unroll
    for (int i = 0; i < 32; i += 8)
        Pb[(size_t)(c0 + y + i) * SEQN + s0 + x] = t[x][y + i];
}

// ---- row softmax over 4096, fp16 in-place ----
__global__ __launch_bounds__(256) void softmax_rows_h_kernel(__half* __restrict__ P)
{
    __shared__ float sh[8];
    size_t base = (size_t)blockIdx.x * SEQN;
    int tid = threadIdx.x, lane = tid & 31, wid = tid >> 5;
    float v[16], m = -1e30f;
#pragma unroll
    for (int i = 0; i < 16; i++) {
        v[i] = __half2float(P[base + tid + i * 256]);
        m = fmaxf(m, v[i]);
    }
#pragma unroll
    for (int o = 16; o; o >>= 1) m = fmaxf(m, __shfl_xor_sync(~0u, m, o));
    if (lane == 0) sh[wid] = m;
    __syncthreads();
    if (tid == 0) { float t = sh[0]; for (int i = 1; i < 8; i++) t = fmaxf(t, sh[i]); sh[0] = t; }
    __syncthreads();
    float M = sh[0];
    __syncthreads();
    float s = 0.f;
#pragma unroll
    for (int i = 0; i < 16; i++) { v[i] = __expf(v[i] - M); s += v[i]; }
#pragma unroll
    for (int o = 16; o; o >>= 1) s += __shfl_xor_sync(~0u, s, o);
    if (lane == 0) sh[wid] = s;
    __syncthreads();
    if (tid == 0) { float t = 0; for (int i = 0; i < 8; i++) t += sh[i]; sh[0] = t; }
    __syncthreads();
    float inv = 1.f / sh[0];
#pragma unroll
    for (int i = 0; i < 16; i++)
        P[base + tid + i * 256] = __float2half_rn(v[i] * inv);
}

// ---- reduce partials + LN for Kc/Vc; fp16 hi outputs only ----
__global__ __launch_bounds__(256) void compress_ln_kernel(
    const float* __restrict__ partK, const float* __restrict__ partV,
    const float* __restrict__ gamma, const float* __restrict__ beta,
    __half* __restrict__ oKh, __half* __restrict__ oVh)
{
    __shared__ float shs[8], shq[8];
    int bl = blockIdx.x, b = bl >> 5, l = bl & 31;
    const float* part = blockIdx.y ? partV : partK;
    __half* outh = blockIdx.y ? oVh : oKh;
    int tid = threadIdx.x, c = tid * 4;
    size_t base = ((size_t)(b * NH + (c >> 6)) * NL + l) * DHD + (c & 63);
    float4 acc = make_float4(0, 0, 0, 0);
#pragma unroll
    for (int sp = 0; sp < NSPLIT; sp++) {
        float4 p = *(const float4*)(part + (size_t)sp * CSIZE + base);
        acc.x += p.x; acc.y += p.y; acc.z += p.z; acc.w += p.w;
    }
    float s = acc.x + acc.y + acc.z + acc.w;
    float q = acc.x*acc.x + acc.y*acc.y + acc.z*acc.z + acc.w*acc.w;
    int lane = tid & 31, wid = tid >> 5;
#pragma unroll
    for (int o = 16; o; o >>= 1) {
        s += __shfl_xor_sync(~0u, s, o); q += __shfl_xor_sync(~0u, q, o);
    }
    if (lane == 0) { shs[wid] = s; shq[wid] = q; }
    __syncthreads();
    if (tid == 0) {
        float ts = 0, tq = 0;
        for (int i = 0; i < 8; i++) { ts += shs[i]; tq += shq[i]; }
        shs[0] = ts; shq[0] = tq;
    }
    __syncthreads();
    float mean = shs[0] * (1.f / DIM);
    float rstd = rsqrtf(shq[0] * (1.f / DIM) - mean * mean + 1e-5f);
    float4 g4 = ((const float4*)gamma)[tid], b4 = ((const float4*)beta)[tid];
    __half2* hp = (__half2*)(outh + base);
    hp[0] = __halves2half2(__float2half_rn((acc.x - mean) * rstd * g4.x + b4.x),
                           __float2half_rn((acc.y - mean) * rstd * g4.y + b4.y));
    hp[1] = __halves2half2(__float2half_rn((acc.z - mean) * rstd * g4.z + b4.z),
                           __float2half_rn((acc.w - mean) * rstd * g4.w + b4.w));
}

// ================= HMMA attention (QK 1-term, PV 1-term) ===================
#define AROWB 144
#define AS_QH 0
#define AS_KH (64 * AROWB)
#define AS_VH (176 * AROWB)
#define ATTN_SMEM (288 * AROWB)    // 41472 B

__global__ __launch_bounds__(128, 3) void attn_hmma(
    const __half* __restrict__ Qh,
    const __half* __restrict__ Kh, const __half* __restrict__ Vh,
    const __half* __restrict__ Kch, const __half* __restrict__ Vch,
    __half* __restrict__ Ch)
{
    extern __shared__ __align__(16) char smem[];
    const uint32_t sb = smem_u32(smem);
    const int h = blockIdx.y, bb = blockIdx.z;
    const int bh = bb * NH + h;
    const int qbase = blockIdx.x * 64;
    const int tid = threadIdx.x, lane = tid & 31, warp = tid >> 5;

    for (int idx = tid; idx < 112 * 8; idx += 128) {
        const int row = idx >> 3, seg = idx & 7;
        const uint32_t dst = row * AROWB + seg * 16;
        uint4 kh4 = {0,0,0,0}, vh4 = {0,0,0,0};
        if (row < 32) {
            size_t src = ((size_t)bh * NL + row) * DHD + seg * 8;
            kh4 = *(const uint4*)(Kch + src);
            vh4 = *(const uint4*)(Vch + src);
        } else {
            const int seq = qbase - EE + (row - 32);
            if (seq >= 0 && seq < SEQN) {
                size_t src = ((size_t)bh * SEQN + seq) * DHD + seg * 8;
                kh4 = *(const uint4*)(Kh + src);
                vh4 = *(const uint4*)(Vh + src);
            }
        }
        *(uint4*)(smem + AS_KH + dst) = kh4;
        *(uint4*)(smem + AS_VH + dst) = vh4;
    }
    for (int idx = tid; idx < 64 * 8; idx += 128) {
        const int row = idx >> 3, seg = idx & 7;
        size_t src = ((size_t)bh * SEQN + qbase + row) * DHD + seg * 8;
        *(uint4*)(smem + AS_QH + row * AROWB + seg * 16) = *(const uint4*)(Qh + src);
    }
    __syncthreads();

    const int r0 = warp * 16;
    float sacc[14][4];
#pragma unroll
    for (int j = 0; j < 14; j++)
#pragma unroll
        for (int e = 0; e < 4; e++) sacc[j][e] = 0.f;

    const uint32_t aOff = (uint32_t)(r0 + (lane & 15)) * AROWB + (lane >> 4) * 16;
    const uint32_t bOffS = (uint32_t)(((lane >> 4) & 1) * 8 + (lane & 7)) * AROWB
                           + ((lane >> 3) & 1) * 16;
#pragma unroll
    for (int ks = 0; ks < 4; ks++) {
        uint32_t ah[4];
        LDSM4(ah, sb + AS_QH + aOff + ks * 32);
#pragma unroll
        for (int i = 0; i < 7; i++) {
            const uint32_t bo = bOffS + (uint32_t)(i * 16) * AROWB + ks * 32;
            uint32_t bh4[4];
            LDSM4(bh4, sb + AS_KH + bo);
            MMA16816(sacc[2*i+0], ah, bh4[0], bh4[1]);
            MMA16816(sacc[2*i+1], ah, bh4[2], bh4[3]);
        }
    }

    const int ra = r0 + (lane >> 2), rb = ra + 8;
    const int ga = ra >> 3, gb = rb >> 3;
    float mxa = -1e30f, mxb = -1e30f;
    bool vld[14][4];
#pragma unroll
    for (int j = 0; j < 14; j++) {
#pragma unroll
        for (int e = 0; e < 2; e++) {
            const int col = j * 8 + (lane & 3) * 2 + e;
            bool va, vb;
            if (col < 32) { va = true; vb = true; }
            else {
                const int w = col - 32;
                const int seq = qbase - EE + w;
                const bool sv = (seq >= 0) && (seq < SEQN);
                va = sv && (w >= ga * 8) && (w < ga * 8 + BAND);
                vb = sv && (w >= gb * 8) && (w < gb * 8 + BAND);
            }
            vld[j][e] = va; vld[j][2 + e] = vb;
            if (va) mxa = fmaxf(mxa, sacc[j][e]);
            if (vb) mxb = fmaxf(mxb, sacc[j][2 + e]);
        }
    }
#pragma unroll
    for (int o = 1; o <= 2; o <<= 1) {
        mxa = fmaxf(mxa, __shfl_xor_sync(~0u, mxa, o));
        mxb = fmaxf(mxb, __shfl_xor_sync(~0u, mxb, o));
    }
    float sma = 0.f, smb = 0.f;
#pragma unroll
    for (int j = 0; j < 14; j++) {
#pragma unroll
        for (int e = 0; e < 2; e++) {
            float pa = vld[j][e]     ? __expf(sacc[j][e]     - mxa) : 0.f;
            float pb = vld[j][2 + e] ? __expf(sacc[j][2 + e] - mxb) : 0.f;
            sacc[j][e] = pa; sacc[j][2 + e] = pb;
            sma += pa; smb += pb;
        }
    }
#pragma unroll
    for (int o = 1; o <= 2; o <<= 1) {
        sma += __shfl_xor_sync(~0u, sma, o);
        smb += __shfl_xor_sync(~0u, smb, o);
    }
    const float iva = 1.f / sma, ivb = 1.f / smb;
#pragma unroll
    for (int j = 0; j < 14; j++) {
        sacc[j][0] *= iva; sacc[j][1] *= iva;
        sacc[j][2] *= ivb; sacc[j][3] *= ivb;
    }

    float pacc[8][4];
#pragma unroll
    for (int i = 0; i < 8; i++)
#pragma unroll
        for (int e = 0; e < 4; e++) pacc[i][e] = 0.f;

    const uint32_t bRowV = (uint32_t)((lane & 7) + ((lane >> 3) & 1) * 8);
    const uint32_t bColV = ((lane >> 4) & 1) * 16;
#pragma unroll
    for (int ks = 0; ks < 7; ks++) {
        const int j0 = 2 * ks, j1 = 2 * ks + 1;
        uint32_t Pf[4];
        Pf[0] = pack_h2(sacc[j0][0], sacc[j0][1]);
        Pf[1] = pack_h2(sacc[j0][2], sacc[j0][3]);
        Pf[2] = pack_h2(sacc[j1][0], sacc[j1][1]);
        Pf[3] = pack_h2(sacc[j1][2], sacc[j1][3]);
        const uint32_t vbase = (uint32_t)(ks * 16 + bRowV) * AROWB + bColV;
#pragma unroll
        for (int m = 0; m < 4; m++) {
            uint32_t bvh[4];
            LDSM4T(bvh, sb + AS_VH + vbase + m * 32);
            MMA16816(pacc[2*m+0], Pf, bvh[0], bvh[1]);
            MMA16816(pacc[2*m+1], Pf, bvh[2], bvh[3]);
        }
    }

    const size_t rowA = ((size_t)(bb * SEQN) + qbase + ra) * DIM + h * DHD;
    const size_t rowB = ((size_t)(bb * SEQN) + qbase + rb) * DIM + h * DHD;
#pragma unroll
    for (int nt = 0; nt < 8; nt++) {
        const int d = nt * 8 + (lane & 3) * 2;
        *(__half2*)(Ch + rowA + d) = __halves2half2(
            __float2half_rn(pacc[nt][0]), __float2half_rn(pacc[nt][1]));
        *(__half2*)(Ch + rowB + d) = __halves2half2(
            __float2half_rn(pacc[nt][2]), __float2half_rn(pacc[nt][3]));
    }
}

// ===========================================================================
extern "C" void kernel_launch(void* const* d_in, const int* in_sizes, int n_in,
                              void* d_out, int out_size)
{
    (void)in_sizes; (void)n_in; (void)out_size;
    const float* query = (const float*)d_in[0];
    const float* Wq = (const float*)d_in[1];  const float* bq = (const float*)d_in[2];
    const float* Wk = (const float*)d_in[3];  const float* bk = (const float*)d_in[4];
    const float* Wv = (const float*)d_in[5];  const float* bv = (const float*)d_in[6];
    const float* Wo = (const float*)d_in[7];  const float* bo = (const float*)d_in[8];
    const float* gl = (const float*)d_in[9];  const float* bl = (const float*)d_in[10];
    const float* gs = (const float*)d_in[11]; const float* bs = (const float*)d_in[12];
    const float* Wd = (const float*)d_in[13]; const float* bd = (const float*)d_in[14];
    float* out = (float*)d_out;

    float *pKcP,*pVcP;
    __half *pD,*pTmp,*pTv,*pXh,*pCh,*pWth,*pQh;
    __half *pKhF,*pVhF,*pPh,*pKch,*pVch;
    cudaGetSymbolAddress((void**)&pTmp, g_tmp);
    cudaGetSymbolAddress((void**)&pTv, g_tv);
    cudaGetSymbolAddress((void**)&pD, g_D);
    cudaGetSymbolAddress((void**)&pKcP, g_KcP);
    cudaGetSymbolAddress((void**)&pVcP, g_VcP);
    cudaGetSymbolAddress((void**)&pXh, g_Xh);
    cudaGetSymbolAddress((void**)&pCh, g_Ch);
    cudaGetSymbolAddress((void**)&pWth, g_Wth);
    cudaGetSymbolAddress((void**)&pQh, g_Qh);
    cudaGetSymbolAddress((void**)&pKhF, g_KhF);
    cudaGetSymbolAddress((void**)&pVhF, g_VhF);
    cudaGetSymbolAddress((void**)&pPh, g_Ph);
    cudaGetSymbolAddress((void**)&pKch, g_Kch);
    cudaGetSymbolAddress((void**)&pVch, g_Vch);

    cudaFuncSetAttribute(hgemm_qkvd, cudaFuncAttributeMaxDynamicSharedMemorySize, GEMM_SMEM1);
    cudaFuncSetAttribute(hgemm_o, cudaFuncAttributeMaxDynamicSharedMemorySize, GEMM_SMEM1);
    cudaFuncSetAttribute(compress_hmma, cudaFuncAttributeMaxDynamicSharedMemorySize, COMP_SMEM);
    cudaFuncSetAttribute(attn_hmma, cudaFuncAttributeMaxDynamicSharedMemorySize, ATTN_SMEM);

    split_perm_kernel<<<MROWS * DIM / 4 / 256, 256>>>(query, pXh);
    wsplit_all_kernel<<<dim3(DIM / 32, DIM / 32, 5), dim3(32, 8)>>>(
        Wq, Wk, Wv, Wd, Wo, pWth);

    hgemm_qkvd<<<dim3((3 * DIM + NH * NL) / 128, MROWS / 128), 256, GEMM_SMEM1>>>(
        pXh, pWth, bq, bk, bv, bd, pQh, pTmp, pTv, pD);

    ln_split2_kernel<<<dim3(MROWS, 2), 128>>>(pTmp, pTv, gl, bl, pKhF, pVhF);

    transpose_h_kernel<<<dim3((NH * NL) / 32, SEQN / 32, BATCH), dim3(32, 8)>>>(pD, pPh);
    softmax_rows_h_kernel<<<BATCH * NH * NL, 256>>>(pPh);

    compress_hmma<<<dim3(BATCH * NH, NSPLIT), 256, COMP_SMEM>>>(
        pPh, pKhF, pVhF, pKcP, pVcP);
    compress_ln_kernel<<<dim3(BATCH * NL, 2), 256>>>(pKcP, pVcP, gs, bs, pKch, pVch);

    attn_hmma<<<dim3(SEQN / 64, NH, BATCH), 128, ATTN_SMEM>>>(
        pQh, pKhF, pVhF, pKch, pVch, pCh);

    hgemm_o<<<dim3(DIM / 128, MROWS / 128), 256, GEMM_SMEM1>>>(
        pCh, pWth + WOFF_O, bo, out);
}